// round 13
// baseline (speedup 1.0000x reference)
#include <cuda_runtime.h>
#include <cuda_bf16.h>
#include <cstdint>

// ---------------------------------------------------------------------------
// Problem constants
// ---------------------------------------------------------------------------
#define B_   4
#define T_   4096
#define D_   1024
#define E_   1024
#define TWOE 2048
#define BT   (B_ * T_)          // 16384 rows
#define EPS_ 1e-8f

// ---------------------------------------------------------------------------
// Scratch (__device__ globals; no runtime allocation allowed)
// ---------------------------------------------------------------------------
__device__ float         g_z1[(size_t)BT * TWOE];     // in_proj pre-norm (fp32)
__device__ float         g_ssq[BT];                   // row sum-of-squares
__device__ __nv_bfloat16 g_uhi[(size_t)BT * D_];
__device__ __nv_bfloat16 g_ulo[(size_t)BT * D_];
__device__ __nv_bfloat16 g_w1hi[(size_t)TWOE * D_];
__device__ __nv_bfloat16 g_w1lo[(size_t)TWOE * D_];
__device__ __nv_bfloat16 g_ghi[(size_t)BT * E_];
__device__ __nv_bfloat16 g_glo[(size_t)BT * E_];
__device__ __nv_bfloat16 g_w2hi[(size_t)D_ * E_];
__device__ __nv_bfloat16 g_w2lo[(size_t)D_ * E_];

// ---------------------------------------------------------------------------
// HMMA split-bf16 GEMM (NT): C[m,n] = sum_k A[m,k]*B[n,k] + bias[n]
//   C = Ahi*Bhi + Alo*Bhi + Ahi*Blo   (fp32 accum; lo*lo dropped)
// Templated on BN (128 for GEMM1, 64 for GEMM2 to kill wave quantization).
// BM=128, GK=32 (two k16 steps per barrier), 8 warps, warp tile 64 x (BN/4).
// 3-stage cp.async circular pipeline (wait_group 1, one barrier per chunk),
// dynamic smem, 2 CTAs/SM.
// Swizzle (64B rows): row r, 16B chunk c -> r*64 + ((c ^ ((r>>1)&3)) * 16).
// Optional: epilogue atomically accumulates per-row sum(C^2) into ssq.
// ---------------------------------------------------------------------------
#define GK 32
#define ROWB 64                   // bytes per smem row (32 bf16)

__device__ __forceinline__ uint32_t smem_u32(const void* p) {
    uint32_t a;
    asm("{ .reg .u64 t; cvta.to.shared.u64 t, %1; cvt.u32.u64 %0, t; }" : "=r"(a) : "l"(p));
    return a;
}
__device__ __forceinline__ void cp_async16(uint32_t dst, const void* src) {
    asm volatile("cp.async.cg.shared.global [%0], [%1], 16;\n" :: "r"(dst), "l"(src));
}
__device__ __forceinline__ void cp_commit() { asm volatile("cp.async.commit_group;\n"); }
template <int N>
__device__ __forceinline__ void cp_wait() { asm volatile("cp.async.wait_group %0;\n" :: "n"(N)); }

__device__ __forceinline__ void ldmat_x4(uint32_t* r, uint32_t addr) {
    asm volatile("ldmatrix.sync.aligned.m8n8.x4.shared.b16 {%0,%1,%2,%3}, [%4];"
                 : "=r"(r[0]), "=r"(r[1]), "=r"(r[2]), "=r"(r[3]) : "r"(addr));
}
__device__ __forceinline__ void mma_bf16(float* d, const uint32_t* a, const uint32_t* b) {
    asm volatile(
        "mma.sync.aligned.m16n8k16.row.col.f32.bf16.bf16.f32 "
        "{%0,%1,%2,%3}, {%4,%5,%6,%7}, {%8,%9}, {%0,%1,%2,%3};"
        : "+f"(d[0]), "+f"(d[1]), "+f"(d[2]), "+f"(d[3])
        : "r"(a[0]), "r"(a[1]), "r"(a[2]), "r"(a[3]), "r"(b[0]), "r"(b[1]));
}

// swizzled byte offset for (row, 16B-chunk 0..3) in a 64B-row tile
__device__ __forceinline__ uint32_t swz(int row, int c16) {
    return (uint32_t)(row * ROWB + ((c16 ^ ((row >> 1) & 3)) * 16));
}

template <int BN>
__global__ __launch_bounds__(256, 2)
void gemm_hmma_bf16x2(const __nv_bfloat16* __restrict__ Ahi, const __nv_bfloat16* __restrict__ Alo,
                      const __nv_bfloat16* __restrict__ Bhi, const __nv_bfloat16* __restrict__ Blo,
                      const float* __restrict__ bias, float* __restrict__ C,
                      int M, int N, int K, float* __restrict__ ssq)
{
    constexpr int BM      = 128;
    constexpr int ATILEB  = 128 * ROWB;            // 8192 B
    constexpr int BTILEB  = BN * ROWB;             // 8192 / 4096 B
    constexpr int STAGEB  = 2 * ATILEB + 2 * BTILEB;
    constexpr int STAGES  = 3;
    constexpr int OFF_ALO = ATILEB;
    constexpr int OFF_BHI = 2 * ATILEB;
    constexpr int OFF_BLO = 2 * ATILEB + BTILEB;
    constexpr int BOPS    = BN * 4;                // cp.async per B tile
    constexpr int LOAD_ITERS = (1024 + 2 * BOPS) / 256;
    constexpr int NJ = BN / 32;                    // 8-wide MMA n-tiles per warp
    constexpr int JP = BN / 64;                    // 16-wide ldmatrix groups

    extern __shared__ char smem[];
    const uint32_t sbase = smem_u32(smem);
    const int tid  = threadIdx.x;
    const int wid  = tid >> 5;
    const int lane = tid & 31;
    const int bm = blockIdx.y * BM;
    const int bn = blockIdx.x * BN;
    const int wm = (wid >> 2) * 64;
    const int wn = (wid & 3) * (BN / 4);

    auto load_stage = [&](int stage, int k0) {
        const uint32_t dst0 = sbase + stage * STAGEB;
        #pragma unroll
        for (int i = 0; i < LOAD_ITERS; ++i) {
            int id = tid + i * 256;
            if (id < 1024) {                       // A tiles: 2 x 128 rows x 4 chunks
                int t   = id >> 9;                 // 0 = hi, 1 = lo
                int w   = id & 511;
                int row = w >> 2;
                int c   = w & 3;
                const __nv_bfloat16* src =
                    (t ? Alo : Ahi) + (size_t)(bm + row) * K + k0 + c * 8;
                cp_async16(dst0 + (t ? OFF_ALO : 0) + swz(row, c), src);
            } else {                               // B tiles: 2 x BN rows x 4 chunks
                int id2 = id - 1024;
                int t   = id2 / BOPS;
                int w   = id2 % BOPS;
                int row = w >> 2;
                int c   = w & 3;
                const __nv_bfloat16* src =
                    (t ? Blo : Bhi) + (size_t)(bn + row) * K + k0 + c * 8;
                cp_async16(dst0 + (t ? OFF_BLO : OFF_BHI) + swz(row, c), src);
            }
        }
        cp_commit();
    };

    float acc[4][NJ][4];
    #pragma unroll
    for (int i = 0; i < 4; ++i)
        #pragma unroll
        for (int j = 0; j < NJ; ++j)
            #pragma unroll
            for (int q = 0; q < 4; ++q) acc[i][j][q] = 0.f;

    const int chunks = K / GK;
    load_stage(0, 0);
    load_stage(1, GK);

    // lane->tile-offset decode for ldmatrix (fixed per lane)
    const int l8  = lane & 7;
    const int sel = lane >> 3;
    const int a_row = (sel & 1) * 8 + l8;
    const int a_c   = sel >> 1;
    const int b_row = (sel >> 1) * 8 + l8;
    const int b_c   = sel & 1;

    uint32_t ra[2][4], rb[2][JP];
    #pragma unroll
    for (int s = 0; s < 2; ++s) {
        #pragma unroll
        for (int mi = 0; mi < 4; ++mi)
            ra[s][mi] = swz(wm + mi * 16 + a_row, 2 * s + a_c);
        #pragma unroll
        for (int jp = 0; jp < JP; ++jp)
            rb[s][jp] = swz(wn + jp * 16 + b_row, 2 * s + b_c);
    }

    int stage = 0;
    for (int ch = 0; ch < chunks; ++ch) {
        cp_wait<1>();
        __syncthreads();
        if (ch + 2 < chunks) {
            int ns = stage + 2; if (ns >= STAGES) ns -= STAGES;
            load_stage(ns, (ch + 2) * GK);
        }

        const uint32_t st = sbase + stage * STAGEB;
        const uint32_t aHiB = st;
        const uint32_t aLoB = st + OFF_ALO;
        const uint32_t bHiB = st + OFF_BHI;
        const uint32_t bLoB = st + OFF_BLO;

        #pragma unroll
        for (int s = 0; s < 2; ++s) {
            uint32_t ahi[4][4], alo[4][4], bhi[NJ][2], blo[NJ][2];
            #pragma unroll
            for (int mi = 0; mi < 4; ++mi) {
                ldmat_x4(ahi[mi], aHiB + ra[s][mi]);
                ldmat_x4(alo[mi], aLoB + ra[s][mi]);
            }
            #pragma unroll
            for (int jp = 0; jp < JP; ++jp) {
                uint32_t th[4], tl[4];
                ldmat_x4(th, bHiB + rb[s][jp]);
                ldmat_x4(tl, bLoB + rb[s][jp]);
                bhi[jp*2  ][0] = th[0]; bhi[jp*2  ][1] = th[1];
                bhi[jp*2+1][0] = th[2]; bhi[jp*2+1][1] = th[3];
                blo[jp*2  ][0] = tl[0]; blo[jp*2  ][1] = tl[1];
                blo[jp*2+1][0] = tl[2]; blo[jp*2+1][1] = tl[3];
            }
            #pragma unroll
            for (int mi = 0; mi < 4; ++mi)
                #pragma unroll
                for (int nj = 0; nj < NJ; ++nj) {
                    mma_bf16(acc[mi][nj], ahi[mi], bhi[nj]);
                    mma_bf16(acc[mi][nj], alo[mi], bhi[nj]);
                    mma_bf16(acc[mi][nj], ahi[mi], blo[nj]);
                }
        }

        ++stage; if (stage >= STAGES) stage = 0;
    }

    // epilogue: frag layout row = lane/4 (+8), col = 2*(lane%4) (+1)
    const int er = lane >> 2;
    const int ec = (lane & 3) * 2;
    #pragma unroll
    for (int mi = 0; mi < 4; ++mi) {
        float pr0 = 0.f, pr1 = 0.f;
        #pragma unroll
        for (int nj = 0; nj < NJ; ++nj) {
            int row0 = bm + wm + mi * 16 + er;
            int col  = bn + wn + nj * 8 + ec;
            float b0 = bias[col], b1 = bias[col + 1];
            float v00 = acc[mi][nj][0] + b0, v01 = acc[mi][nj][1] + b1;
            float v10 = acc[mi][nj][2] + b0, v11 = acc[mi][nj][3] + b1;
            *(float2*)&C[(size_t)row0 * N + col]       = make_float2(v00, v01);
            *(float2*)&C[(size_t)(row0 + 8) * N + col] = make_float2(v10, v11);
            pr0 += v00 * v00 + v01 * v01;
            pr1 += v10 * v10 + v11 * v11;
        }
        if (ssq) {
            int row0 = bm + wm + mi * 16 + er;
            #pragma unroll
            for (int o = 1; o < 4; o <<= 1) {
                pr0 += __shfl_xor_sync(0xffffffff, pr0, o);
                pr1 += __shfl_xor_sync(0xffffffff, pr1, o);
            }
            if ((lane & 3) == 0) {
                atomicAdd(&ssq[row0],     pr0);
                atomicAdd(&ssq[row0 + 8], pr1);
            }
        }
    }
}

// ---------------------------------------------------------------------------
// Elementwise kernels
// ---------------------------------------------------------------------------
__global__ void zero_f32(float* __restrict__ p, int n)
{
    int i = blockIdx.x * blockDim.x + threadIdx.x;
    if (i < n) p[i] = 0.f;
}

// One launch handling all three fp32->bf16 hi/lo splits (u, W_in, W_out).
#define N4_U  (BT * D_ / 4)
#define N4_W1 (TWOE * D_ / 4)
#define N4_W2 (D_ * E_ / 4)
#define N4_ALL (N4_U + N4_W1 + N4_W2)

__global__ void split_all_bf16(const float* __restrict__ u,
                               const float* __restrict__ W1,
                               const float* __restrict__ W2,
                               __nv_bfloat16* __restrict__ uhi, __nv_bfloat16* __restrict__ ulo,
                               __nv_bfloat16* __restrict__ w1hi, __nv_bfloat16* __restrict__ w1lo,
                               __nv_bfloat16* __restrict__ w2hi, __nv_bfloat16* __restrict__ w2lo)
{
    int i = blockIdx.x * blockDim.x + threadIdx.x;
    if (i >= N4_ALL) return;
    const float* src;
    __nv_bfloat16 *hi, *lo;
    int j;
    if (i < N4_U)              { src = u;  hi = uhi;  lo = ulo;  j = i; }
    else if (i < N4_U + N4_W1) { src = W1; hi = w1hi; lo = w1lo; j = i - N4_U; }
    else                       { src = W2; hi = w2hi; lo = w2lo; j = i - N4_U - N4_W1; }

    float4 v = ((const float4*)src)[j];
    __nv_bfloat16 h[4], l[4];
    float f[4] = {v.x, v.y, v.z, v.w};
    #pragma unroll
    for (int k = 0; k < 4; ++k) {
        h[k] = __float2bfloat16(f[k]);
        l[k] = __float2bfloat16(f[k] - __bfloat162float(h[k]));
    }
    ((uint2*)hi)[j] = *(uint2*)h;
    ((uint2*)lo)[j] = *(uint2*)l;
}

// conv(K=3,'same') + gate; row scales computed inline from ssq.
__global__ void conv_gate(const float* __restrict__ z1, const float* __restrict__ ssq,
                          const float* __restrict__ innw,
                          const float* __restrict__ cw, const float* __restrict__ cb,
                          __nv_bfloat16* __restrict__ ghi, __nv_bfloat16* __restrict__ glo)
{
    const int idx = blockIdx.x * blockDim.x + threadIdx.x;   // over BT*E
    const int e   = idx & (E_ - 1);
    const int row = idx >> 10;
    const int t   = row & (T_ - 1);

    const float wn  = innw[e];
    const float wnv = innw[E_ + e];
    const float w0 = cw[e * 3 + 0], w1 = cw[e * 3 + 1], w2 = cw[e * 3 + 2];
    const float kinv = 1.0f / TWOE;

    const float sc = rsqrtf(ssq[row] * kinv + EPS_);
    float xm = cb[e];
    if (t > 0) {
        float s0 = rsqrtf(ssq[row - 1] * kinv + EPS_);
        xm = fmaf(w0, z1[(size_t)(row - 1) * TWOE + e] * s0 * wn, xm);
    }
    xm = fmaf(w1, z1[(size_t)row * TWOE + e] * sc * wn, xm);
    if (t < T_ - 1) {
        float s2 = rsqrtf(ssq[row + 1] * kinv + EPS_);
        xm = fmaf(w2, z1[(size_t)(row + 1) * TWOE + e] * s2 * wn, xm);
    }
    const float v = z1[(size_t)row * TWOE + E_ + e] * sc * wnv;
    const float g = v * xm;
    __nv_bfloat16 h = __float2bfloat16(g);
    ghi[idx] = h;
    glo[idx] = __float2bfloat16(g - __bfloat162float(h));
}

__global__ void out_rmsnorm(float* __restrict__ out, const float* __restrict__ w)
{
    const int row = blockIdx.x;
    float4* p = (float4*)(out + (size_t)row * D_);
    float4 v = p[threadIdx.x];                  // 256 x 4 = 1024
    float acc = v.x*v.x + v.y*v.y + v.z*v.z + v.w*v.w;
    #pragma unroll
    for (int o = 16; o > 0; o >>= 1) acc += __shfl_xor_sync(0xffffffff, acc, o);
    __shared__ float warpsum[8];
    __shared__ float s_bcast;
    if ((threadIdx.x & 31) == 0) warpsum[threadIdx.x >> 5] = acc;
    __syncthreads();
    if (threadIdx.x == 0) {
        float tsum = 0.f;
        #pragma unroll
        for (int wi = 0; wi < 8; ++wi) tsum += warpsum[wi];
        s_bcast = rsqrtf(tsum * (1.0f / D_) + EPS_);
    }
    __syncthreads();
    const float s = s_bcast;
    float4 wv = *(const float4*)&w[threadIdx.x * 4];
    v.x *= s * wv.x; v.y *= s * wv.y; v.z *= s * wv.z; v.w *= s * wv.w;
    p[threadIdx.x] = v;
}

// ---------------------------------------------------------------------------
// Launch
// Inputs (metadata order): u, W_in, b_in, in_norm_w, conv_w, conv_b,
//                          W_out, b_out, out_norm_w
// ---------------------------------------------------------------------------
#define SMEM_128 (3 * (2 * 128 * ROWB + 2 * 128 * ROWB))   // 98304
#define SMEM_64  (3 * (2 * 128 * ROWB + 2 * 64 * ROWB))    // 73728

extern "C" void kernel_launch(void* const* d_in, const int* in_sizes, int n_in,
                              void* d_out, int out_size)
{
    const float* u      = (const float*)d_in[0];
    const float* W_in   = (const float*)d_in[1];
    const float* b_in   = (const float*)d_in[2];
    const float* innw   = (const float*)d_in[3];
    const float* conv_w = (const float*)d_in[4];
    const float* conv_b = (const float*)d_in[5];
    const float* W_out  = (const float*)d_in[6];
    const float* b_out  = (const float*)d_in[7];
    const float* outnw  = (const float*)d_in[8];
    float* out = (float*)d_out;

    float *z1, *ssq;
    __nv_bfloat16 *uhi, *ulo, *w1hi, *w1lo, *ghi, *glo, *w2hi, *w2lo;
    cudaGetSymbolAddress((void**)&z1,   g_z1);
    cudaGetSymbolAddress((void**)&ssq,  g_ssq);
    cudaGetSymbolAddress((void**)&uhi,  g_uhi);
    cudaGetSymbolAddress((void**)&ulo,  g_ulo);
    cudaGetSymbolAddress((void**)&w1hi, g_w1hi);
    cudaGetSymbolAddress((void**)&w1lo, g_w1lo);
    cudaGetSymbolAddress((void**)&ghi,  g_ghi);
    cudaGetSymbolAddress((void**)&glo,  g_glo);
    cudaGetSymbolAddress((void**)&w2hi, g_w2hi);
    cudaGetSymbolAddress((void**)&w2lo, g_w2lo);

    cudaFuncSetAttribute(gemm_hmma_bf16x2<128>,
                         cudaFuncAttributeMaxDynamicSharedMemorySize, SMEM_128);
    cudaFuncSetAttribute(gemm_hmma_bf16x2<64>,
                         cudaFuncAttributeMaxDynamicSharedMemorySize, SMEM_64);

    // 0) zero row sum-of-squares
    zero_f32<<<(BT + 255) / 256, 256>>>(ssq, BT);

    // 1) split inputs/weights to bf16 hi/lo (single launch)
    split_all_bf16<<<(N4_ALL + 255) / 256, 256>>>(u, W_in, W_out,
                                                  uhi, ulo, w1hi, w1lo, w2hi, w2lo);

    // 2) in_proj GEMM (HMMA) + bias -> z1; ssq fused in epilogue
    {
        dim3 grid(TWOE / 128, BT / 128);
        gemm_hmma_bf16x2<128><<<grid, 256, SMEM_128>>>(uhi, ulo, w1hi, w1lo, b_in, z1,
                                                       BT, TWOE, D_, ssq);
    }
    // 3) conv + gate (row scales inline) -> gated bf16 hi/lo
    conv_gate<<<(BT * E_) / 256, 256>>>(z1, ssq, innw, conv_w, conv_b, ghi, glo);

    // 4) out_proj GEMM + bias -> out (raw); BN=64 kills wave quantization
    {
        dim3 grid(D_ / 64, BT / 128);
        gemm_hmma_bf16x2<64><<<grid, 256, SMEM_64>>>(ghi, glo, w2hi, w2lo, b_out, out,
                                                     BT, D_, E_, nullptr);
    }
    // 5) in-place RMSNorm on out rows
    out_rmsnorm<<<BT, 256>>>(out, outnw);
}

// round 14
// speedup vs baseline: 1.0662x; 1.0662x over previous
#include <cuda_runtime.h>
#include <cuda_bf16.h>
#include <cstdint>

// ---------------------------------------------------------------------------
// Problem constants
// ---------------------------------------------------------------------------
#define B_   4
#define T_   4096
#define D_   1024
#define E_   1024
#define TWOE 2048
#define BT   (B_ * T_)          // 16384 rows
#define EPS_ 1e-8f

// ---------------------------------------------------------------------------
// Scratch (__device__ globals; no runtime allocation allowed)
// ---------------------------------------------------------------------------
__device__ float         g_z1[(size_t)BT * TWOE];     // in_proj pre-norm (fp32)
__device__ float         g_ssq[BT];                   // row sum-of-squares
__device__ float         g_s1[BT];                    // row rsqrt scale
__device__ __nv_bfloat16 g_uhi[(size_t)BT * D_];
__device__ __nv_bfloat16 g_ulo[(size_t)BT * D_];
__device__ __nv_bfloat16 g_w1hi[(size_t)TWOE * D_];
__device__ __nv_bfloat16 g_w1lo[(size_t)TWOE * D_];
__device__ __nv_bfloat16 g_ghi[(size_t)BT * E_];
__device__ __nv_bfloat16 g_glo[(size_t)BT * E_];
__device__ __nv_bfloat16 g_w2hi[(size_t)D_ * E_];
__device__ __nv_bfloat16 g_w2lo[(size_t)D_ * E_];

// ---------------------------------------------------------------------------
// HMMA split-bf16 GEMM (NT): C[m,n] = sum_k A[m,k]*B[n,k] + bias[n]
//   C = Ahi*Bhi + Alo*Bhi + Ahi*Blo   (fp32 accum; lo*lo dropped)
// 128x128 CTA tile, GK=32 (two k16 steps per barrier), 8 warps (64x32 warp
// tile), 3-stage cp.async circular pipeline (wait_group 1, one barrier per
// chunk), 96KB dynamic smem, 2 CTAs/SM.  [R10-measured optimum; unchanged]
// Swizzle (64B rows): row r, 16B chunk c -> r*64 + ((c ^ ((r>>1)&3)) * 16).
// Optional: epilogue atomically accumulates per-row sum(C^2) into ssq.
// ---------------------------------------------------------------------------
#define GM 128
#define GN 128
#define GK 32
#define ROWB 64                   // bytes per smem row (32 bf16)
#define TILEB (128 * ROWB)        // 8192 B per tile
#define STAGEB (4 * TILEB)        // 32768 B (Ahi, Alo, Bhi, Blo)
#define STAGES 3
#define GEMM_SMEM (STAGES * STAGEB)   // 98304 B

__device__ __forceinline__ uint32_t smem_u32(const void* p) {
    uint32_t a;
    asm("{ .reg .u64 t; cvta.to.shared.u64 t, %1; cvt.u32.u64 %0, t; }" : "=r"(a) : "l"(p));
    return a;
}
__device__ __forceinline__ void cp_async16(uint32_t dst, const void* src) {
    asm volatile("cp.async.cg.shared.global [%0], [%1], 16;\n" :: "r"(dst), "l"(src));
}
__device__ __forceinline__ void cp_commit() { asm volatile("cp.async.commit_group;\n"); }
template <int N>
__device__ __forceinline__ void cp_wait() { asm volatile("cp.async.wait_group %0;\n" :: "n"(N)); }

__device__ __forceinline__ void ldmat_x4(uint32_t* r, uint32_t addr) {
    asm volatile("ldmatrix.sync.aligned.m8n8.x4.shared.b16 {%0,%1,%2,%3}, [%4];"
                 : "=r"(r[0]), "=r"(r[1]), "=r"(r[2]), "=r"(r[3]) : "r"(addr));
}
__device__ __forceinline__ void mma_bf16(float* d, const uint32_t* a, const uint32_t* b) {
    asm volatile(
        "mma.sync.aligned.m16n8k16.row.col.f32.bf16.bf16.f32 "
        "{%0,%1,%2,%3}, {%4,%5,%6,%7}, {%8,%9}, {%0,%1,%2,%3};"
        : "+f"(d[0]), "+f"(d[1]), "+f"(d[2]), "+f"(d[3])
        : "r"(a[0]), "r"(a[1]), "r"(a[2]), "r"(a[3]), "r"(b[0]), "r"(b[1]));
}

// swizzled byte offset within one 128x32 tile for (row, 16B-chunk 0..3)
__device__ __forceinline__ uint32_t swz(int row, int c16) {
    return (uint32_t)(row * ROWB + ((c16 ^ ((row >> 1) & 3)) * 16));
}

__global__ __launch_bounds__(256, 2)
void gemm_hmma_bf16x2(const __nv_bfloat16* __restrict__ Ahi, const __nv_bfloat16* __restrict__ Alo,
                      const __nv_bfloat16* __restrict__ Bhi, const __nv_bfloat16* __restrict__ Blo,
                      const float* __restrict__ bias, float* __restrict__ C,
                      int M, int N, int K, float* __restrict__ ssq)
{
    extern __shared__ char smem[];
    const uint32_t sbase = smem_u32(smem);
    const int tid  = threadIdx.x;
    const int wid  = tid >> 5;
    const int lane = tid & 31;
    const int bm = blockIdx.y * GM;
    const int bn = blockIdx.x * GN;
    const int wm = (wid >> 2) * 64;            // 0 / 64
    const int wn = (wid & 3) * 32;             // 0 / 32 / 64 / 96

    // stage loader: 4 tiles x 128 rows x 4 chunks(16B) = 2048 cp.async / 256 thr
    auto load_stage = [&](int stage, int k0) {
        const uint32_t dst0 = sbase + stage * STAGEB;
        #pragma unroll
        for (int i = 0; i < 8; ++i) {
            int id  = tid + i * 256;           // 0..2047
            int t   = id >> 9;                 // tile 0..3
            int w   = id & 511;
            int row = w >> 2;
            int c   = w & 3;
            const __nv_bfloat16* src;
            if      (t == 0) src = Ahi + (size_t)(bm + row) * K + k0 + c * 8;
            else if (t == 1) src = Alo + (size_t)(bm + row) * K + k0 + c * 8;
            else if (t == 2) src = Bhi + (size_t)(bn + row) * K + k0 + c * 8;
            else             src = Blo + (size_t)(bn + row) * K + k0 + c * 8;
            cp_async16(dst0 + t * TILEB + swz(row, c), src);
        }
        cp_commit();
    };

    float acc[4][4][4];
    #pragma unroll
    for (int i = 0; i < 4; ++i)
        #pragma unroll
        for (int j = 0; j < 4; ++j)
            #pragma unroll
            for (int q = 0; q < 4; ++q) acc[i][j][q] = 0.f;

    const int chunks = K / GK;
    load_stage(0, 0);
    load_stage(1, GK);

    // lane->tile-offset decode for ldmatrix (fixed per lane)
    const int l8  = lane & 7;
    const int sel = lane >> 3;                 // 0..3
    const int a_row = (sel & 1) * 8 + l8;
    const int a_c   = sel >> 1;
    const int b_row = (sel >> 1) * 8 + l8;
    const int b_c   = sel & 1;

    uint32_t ra[2][4], rb[2][2];
    #pragma unroll
    for (int s = 0; s < 2; ++s) {
        #pragma unroll
        for (int mi = 0; mi < 4; ++mi)
            ra[s][mi] = swz(wm + mi * 16 + a_row, 2 * s + a_c);
        #pragma unroll
        for (int jp = 0; jp < 2; ++jp)
            rb[s][jp] = swz(wn + jp * 16 + b_row, 2 * s + b_c);
    }

    int stage = 0;
    for (int ch = 0; ch < chunks; ++ch) {
        cp_wait<1>();
        __syncthreads();
        if (ch + 2 < chunks) {
            int ns = stage + 2; if (ns >= STAGES) ns -= STAGES;
            load_stage(ns, (ch + 2) * GK);
        }

        const uint32_t st = sbase + stage * STAGEB;
        const uint32_t aHiB = st + 0 * TILEB;
        const uint32_t aLoB = st + 1 * TILEB;
        const uint32_t bHiB = st + 2 * TILEB;
        const uint32_t bLoB = st + 3 * TILEB;

        #pragma unroll
        for (int s = 0; s < 2; ++s) {
            uint32_t ahi[4][4], alo[4][4], bhi[4][2], blo[4][2];
            #pragma unroll
            for (int mi = 0; mi < 4; ++mi) {
                ldmat_x4(ahi[mi], aHiB + ra[s][mi]);
                ldmat_x4(alo[mi], aLoB + ra[s][mi]);
            }
            #pragma unroll
            for (int jp = 0; jp < 2; ++jp) {
                uint32_t th[4], tl[4];
                ldmat_x4(th, bHiB + rb[s][jp]);
                ldmat_x4(tl, bLoB + rb[s][jp]);
                bhi[jp*2  ][0] = th[0]; bhi[jp*2  ][1] = th[1];
                bhi[jp*2+1][0] = th[2]; bhi[jp*2+1][1] = th[3];
                blo[jp*2  ][0] = tl[0]; blo[jp*2  ][1] = tl[1];
                blo[jp*2+1][0] = tl[2]; blo[jp*2+1][1] = tl[3];
            }
            #pragma unroll
            for (int mi = 0; mi < 4; ++mi)
                #pragma unroll
                for (int nj = 0; nj < 4; ++nj) {
                    mma_bf16(acc[mi][nj], ahi[mi], bhi[nj]);
                    mma_bf16(acc[mi][nj], alo[mi], bhi[nj]);
                    mma_bf16(acc[mi][nj], ahi[mi], blo[nj]);
                }
        }

        ++stage; if (stage >= STAGES) stage = 0;
    }

    // epilogue: frag layout row = lane/4 (+8), col = 2*(lane%4) (+1)
    const int er = lane >> 2;
    const int ec = (lane & 3) * 2;
    #pragma unroll
    for (int mi = 0; mi < 4; ++mi) {
        float pr0 = 0.f, pr1 = 0.f;
        #pragma unroll
        for (int nj = 0; nj < 4; ++nj) {
            int row0 = bm + wm + mi * 16 + er;
            int col  = bn + wn + nj * 8 + ec;
            float b0 = bias[col], b1 = bias[col + 1];
            float v00 = acc[mi][nj][0] + b0, v01 = acc[mi][nj][1] + b1;
            float v10 = acc[mi][nj][2] + b0, v11 = acc[mi][nj][3] + b1;
            *(float2*)&C[(size_t)row0 * N + col]       = make_float2(v00, v01);
            *(float2*)&C[(size_t)(row0 + 8) * N + col] = make_float2(v10, v11);
            pr0 += v00 * v00 + v01 * v01;
            pr1 += v10 * v10 + v11 * v11;
        }
        if (ssq) {
            int row0 = bm + wm + mi * 16 + er;
            #pragma unroll
            for (int o = 1; o < 4; o <<= 1) {
                pr0 += __shfl_xor_sync(0xffffffff, pr0, o);
                pr1 += __shfl_xor_sync(0xffffffff, pr1, o);
            }
            if ((lane & 3) == 0) {
                atomicAdd(&ssq[row0],     pr0);
                atomicAdd(&ssq[row0 + 8], pr1);
            }
        }
    }
}

// ---------------------------------------------------------------------------
// Elementwise kernels
// ---------------------------------------------------------------------------
__global__ void zero_f32(float* __restrict__ p, int n)
{
    int i = blockIdx.x * blockDim.x + threadIdx.x;
    if (i < n) p[i] = 0.f;
}

__global__ void split_bf16(const float* __restrict__ x,
                           __nv_bfloat16* __restrict__ hi, __nv_bfloat16* __restrict__ lo,
                           int n4)
{
    int i = blockIdx.x * blockDim.x + threadIdx.x;
    if (i >= n4) return;
    float4 v = ((const float4*)x)[i];
    __nv_bfloat16 h[4], l[4];
    float f[4] = {v.x, v.y, v.z, v.w};
    #pragma unroll
    for (int j = 0; j < 4; ++j) {
        h[j] = __float2bfloat16(f[j]);
        l[j] = __float2bfloat16(f[j] - __bfloat162float(h[j]));
    }
    ((uint2*)hi)[i] = *(uint2*)h;
    ((uint2*)lo)[i] = *(uint2*)l;
}

__global__ void s1_from_ssq(const float* __restrict__ ssq, float* __restrict__ s, int n)
{
    int i = blockIdx.x * blockDim.x + threadIdx.x;
    if (i < n) s[i] = rsqrtf(ssq[i] * (1.0f / TWOE) + EPS_);
}

// conv(K=3,'same') + gate, vectorized by 4 along e.
// Each thread: 4 consecutive e values of one (b,t) row.
__global__ void conv_gate_v4(const float* __restrict__ z1, const float* __restrict__ s1,
                             const float* __restrict__ innw,
                             const float* __restrict__ cw, const float* __restrict__ cb,
                             __nv_bfloat16* __restrict__ ghi, __nv_bfloat16* __restrict__ glo)
{
    const int i   = blockIdx.x * blockDim.x + threadIdx.x;   // over BT*E/4
    const int g   = i & (E_ / 4 - 1);                        // float4 group in row
    const int row = i >> 8;                                  // E/4 = 256 groups/row
    const int t   = row & (T_ - 1);
    const int e   = g * 4;

    const float4 wn  = *(const float4*)&innw[e];
    const float4 wnv = *(const float4*)&innw[E_ + e];
    // conv weights for 4 channels: 12 consecutive floats (16B-aligned since e%4==0)
    const float4 cwa = *(const float4*)&cw[e * 3];
    const float4 cwb = *(const float4*)&cw[e * 3 + 4];
    const float4 cwc = *(const float4*)&cw[e * 3 + 8];
    const float w0[4] = {cwa.x, cwa.w, cwb.z, cwc.y};
    const float w1[4] = {cwa.y, cwb.x, cwb.w, cwc.z};
    const float w2[4] = {cwa.z, cwb.y, cwc.x, cwc.w};
    const float4 cb4 = *(const float4*)&cb[e];

    const float sc = s1[row];
    const float4 zc = *(const float4*)&z1[(size_t)row * TWOE + e];
    const float4 zv = *(const float4*)&z1[(size_t)row * TWOE + E_ + e];

    float xm[4] = {cb4.x, cb4.y, cb4.z, cb4.w};
    const float zcv[4] = {zc.x, zc.y, zc.z, zc.w};
    const float wnv4[4] = {wn.x, wn.y, wn.z, wn.w};

    if (t > 0) {
        const float sp = s1[row - 1];
        const float4 zp = *(const float4*)&z1[(size_t)(row - 1) * TWOE + e];
        const float zpv[4] = {zp.x, zp.y, zp.z, zp.w};
        #pragma unroll
        for (int k = 0; k < 4; ++k)
            xm[k] = fmaf(w0[k], zpv[k] * sp * wnv4[k], xm[k]);
    }
    #pragma unroll
    for (int k = 0; k < 4; ++k)
        xm[k] = fmaf(w1[k], zcv[k] * sc * wnv4[k], xm[k]);
    if (t < T_ - 1) {
        const float sn = s1[row + 1];
        const float4 zn = *(const float4*)&z1[(size_t)(row + 1) * TWOE + e];
        const float znv[4] = {zn.x, zn.y, zn.z, zn.w};
        #pragma unroll
        for (int k = 0; k < 4; ++k)
            xm[k] = fmaf(w2[k], znv[k] * sn * wnv4[k], xm[k]);
    }

    const float vv[4]  = {zv.x, zv.y, zv.z, zv.w};
    const float wv4[4] = {wnv.x, wnv.y, wnv.z, wnv.w};
    __nv_bfloat16 h[4], l[4];
    #pragma unroll
    for (int k = 0; k < 4; ++k) {
        const float gval = (vv[k] * sc * wv4[k]) * xm[k];
        h[k] = __float2bfloat16(gval);
        l[k] = __float2bfloat16(gval - __bfloat162float(h[k]));
    }
    ((uint2*)ghi)[i] = *(uint2*)h;
    ((uint2*)glo)[i] = *(uint2*)l;
}

__global__ void out_rmsnorm(float* __restrict__ out, const float* __restrict__ w)
{
    const int row = blockIdx.x;
    float4* p = (float4*)(out + (size_t)row * D_);
    float4 v = p[threadIdx.x];                  // 256 x 4 = 1024
    float acc = v.x*v.x + v.y*v.y + v.z*v.z + v.w*v.w;
    #pragma unroll
    for (int o = 16; o > 0; o >>= 1) acc += __shfl_xor_sync(0xffffffff, acc, o);
    __shared__ float warpsum[8];
    __shared__ float s_bcast;
    if ((threadIdx.x & 31) == 0) warpsum[threadIdx.x >> 5] = acc;
    __syncthreads();
    if (threadIdx.x == 0) {
        float tsum = 0.f;
        #pragma unroll
        for (int wi = 0; wi < 8; ++wi) tsum += warpsum[wi];
        s_bcast = rsqrtf(tsum * (1.0f / D_) + EPS_);
    }
    __syncthreads();
    const float s = s_bcast;
    float4 wv = *(const float4*)&w[threadIdx.x * 4];
    v.x *= s * wv.x; v.y *= s * wv.y; v.z *= s * wv.z; v.w *= s * wv.w;
    p[threadIdx.x] = v;
}

// ---------------------------------------------------------------------------
// Launch
// Inputs (metadata order): u, W_in, b_in, in_norm_w, conv_w, conv_b,
//                          W_out, b_out, out_norm_w
// ---------------------------------------------------------------------------
extern "C" void kernel_launch(void* const* d_in, const int* in_sizes, int n_in,
                              void* d_out, int out_size)
{
    const float* u      = (const float*)d_in[0];
    const float* W_in   = (const float*)d_in[1];
    const float* b_in   = (const float*)d_in[2];
    const float* innw   = (const float*)d_in[3];
    const float* conv_w = (const float*)d_in[4];
    const float* conv_b = (const float*)d_in[5];
    const float* W_out  = (const float*)d_in[6];
    const float* b_out  = (const float*)d_in[7];
    const float* outnw  = (const float*)d_in[8];
    float* out = (float*)d_out;

    float *z1, *ssq, *s1;
    __nv_bfloat16 *uhi, *ulo, *w1hi, *w1lo, *ghi, *glo, *w2hi, *w2lo;
    cudaGetSymbolAddress((void**)&z1,   g_z1);
    cudaGetSymbolAddress((void**)&ssq,  g_ssq);
    cudaGetSymbolAddress((void**)&s1,   g_s1);
    cudaGetSymbolAddress((void**)&uhi,  g_uhi);
    cudaGetSymbolAddress((void**)&ulo,  g_ulo);
    cudaGetSymbolAddress((void**)&w1hi, g_w1hi);
    cudaGetSymbolAddress((void**)&w1lo, g_w1lo);
    cudaGetSymbolAddress((void**)&ghi,  g_ghi);
    cudaGetSymbolAddress((void**)&glo,  g_glo);
    cudaGetSymbolAddress((void**)&w2hi, g_w2hi);
    cudaGetSymbolAddress((void**)&w2lo, g_w2lo);

    cudaFuncSetAttribute(gemm_hmma_bf16x2,
                         cudaFuncAttributeMaxDynamicSharedMemorySize, GEMM_SMEM);

    // 0) zero row sum-of-squares
    zero_f32<<<(BT + 255) / 256, 256>>>(ssq, BT);

    // 1) split inputs/weights to bf16 hi/lo
    split_bf16<<<((BT * D_ / 4) + 255) / 256, 256>>>(u,     uhi,  ulo,  BT * D_ / 4);
    split_bf16<<<((TWOE * D_ / 4) + 255) / 256, 256>>>(W_in, w1hi, w1lo, TWOE * D_ / 4);
    split_bf16<<<((D_ * E_ / 4) + 255) / 256, 256>>>(W_out, w2hi, w2lo, D_ * E_ / 4);

    // 2) in_proj GEMM (HMMA) + bias -> z1; ssq fused in epilogue
    {
        dim3 grid(TWOE / GN, BT / GM);
        gemm_hmma_bf16x2<<<grid, 256, GEMM_SMEM>>>(uhi, ulo, w1hi, w1lo, b_in, z1,
                                                   BT, TWOE, D_, ssq);
    }
    // 3) row scale from fused ssq
    s1_from_ssq<<<(BT + 255) / 256, 256>>>(ssq, s1, BT);

    // 4) conv + gate (vectorized x4) -> gated bf16 hi/lo
    conv_gate_v4<<<(BT * E_ / 4) / 256, 256>>>(z1, s1, innw, conv_w, conv_b, ghi, glo);

    // 5) out_proj GEMM + bias -> out (raw)
    {
        dim3 grid(D_ / GN, BT / GM);
        gemm_hmma_bf16x2<<<grid, 256, GEMM_SMEM>>>(ghi, glo, w2hi, w2lo, b_out, out,
                                                   BT, D_, E_, nullptr);
    }
    // 6) in-place RMSNorm on out rows
    out_rmsnorm<<<BT, 256>>>(out, outnw);
}

// round 15
// speedup vs baseline: 1.0692x; 1.0028x over previous
#include <cuda_runtime.h>
#include <cuda_bf16.h>
#include <cstdint>

// ---------------------------------------------------------------------------
// Problem constants
// ---------------------------------------------------------------------------
#define B_   4
#define T_   4096
#define D_   1024
#define E_   1024
#define TWOE 2048
#define BT   (B_ * T_)          // 16384 rows
#define EPS_ 1e-8f

// ---------------------------------------------------------------------------
// Scratch (__device__ globals; no runtime allocation allowed)
// ---------------------------------------------------------------------------
__device__ float         g_z1[(size_t)BT * TWOE];     // in_proj pre-norm (fp32)
__device__ float         g_ssq[BT];                   // row sum-of-squares
__device__ __nv_bfloat16 g_uhi[(size_t)BT * D_];
__device__ __nv_bfloat16 g_ulo[(size_t)BT * D_];
__device__ __nv_bfloat16 g_w1hi[(size_t)TWOE * D_];
__device__ __nv_bfloat16 g_w1lo[(size_t)TWOE * D_];
__device__ __nv_bfloat16 g_ghi[(size_t)BT * E_];
__device__ __nv_bfloat16 g_glo[(size_t)BT * E_];
__device__ __nv_bfloat16 g_w2hi[(size_t)D_ * E_];
__device__ __nv_bfloat16 g_w2lo[(size_t)D_ * E_];

// ---------------------------------------------------------------------------
// HMMA split-bf16 GEMM (NT): C[m,n] = sum_k A[m,k]*B[n,k] + bias[n]
//   C = Ahi*Bhi + Alo*Bhi + Ahi*Blo   (fp32 accum; lo*lo dropped)
// 128x128 CTA tile, GK=32 (two k16 steps per barrier), 8 warps (64x32 warp
// tile), 3-stage cp.async circular pipeline (wait_group 1, one barrier per
// chunk), 96KB dynamic smem, 2 CTAs/SM.  [R10/R14-measured optimum; unchanged]
// Swizzle (64B rows): row r, 16B chunk c -> r*64 + ((c ^ ((r>>1)&3)) * 16).
// Optional: epilogue atomically accumulates per-row sum(C^2) into ssq.
// ---------------------------------------------------------------------------
#define GM 128
#define GN 128
#define GK 32
#define ROWB 64                   // bytes per smem row (32 bf16)
#define TILEB (128 * ROWB)        // 8192 B per tile
#define STAGEB (4 * TILEB)        // 32768 B (Ahi, Alo, Bhi, Blo)
#define STAGES 3
#define GEMM_SMEM (STAGES * STAGEB)   // 98304 B

__device__ __forceinline__ uint32_t smem_u32(const void* p) {
    uint32_t a;
    asm("{ .reg .u64 t; cvta.to.shared.u64 t, %1; cvt.u32.u64 %0, t; }" : "=r"(a) : "l"(p));
    return a;
}
__device__ __forceinline__ void cp_async16(uint32_t dst, const void* src) {
    asm volatile("cp.async.cg.shared.global [%0], [%1], 16;\n" :: "r"(dst), "l"(src));
}
__device__ __forceinline__ void cp_commit() { asm volatile("cp.async.commit_group;\n"); }
template <int N>
__device__ __forceinline__ void cp_wait() { asm volatile("cp.async.wait_group %0;\n" :: "n"(N)); }

__device__ __forceinline__ void ldmat_x4(uint32_t* r, uint32_t addr) {
    asm volatile("ldmatrix.sync.aligned.m8n8.x4.shared.b16 {%0,%1,%2,%3}, [%4];"
                 : "=r"(r[0]), "=r"(r[1]), "=r"(r[2]), "=r"(r[3]) : "r"(addr));
}
__device__ __forceinline__ void mma_bf16(float* d, const uint32_t* a, const uint32_t* b) {
    asm volatile(
        "mma.sync.aligned.m16n8k16.row.col.f32.bf16.bf16.f32 "
        "{%0,%1,%2,%3}, {%4,%5,%6,%7}, {%8,%9}, {%0,%1,%2,%3};"
        : "+f"(d[0]), "+f"(d[1]), "+f"(d[2]), "+f"(d[3])
        : "r"(a[0]), "r"(a[1]), "r"(a[2]), "r"(a[3]), "r"(b[0]), "r"(b[1]));
}

// swizzled byte offset within one 128x32 tile for (row, 16B-chunk 0..3)
__device__ __forceinline__ uint32_t swz(int row, int c16) {
    return (uint32_t)(row * ROWB + ((c16 ^ ((row >> 1) & 3)) * 16));
}

__global__ __launch_bounds__(256, 2)
void gemm_hmma_bf16x2(const __nv_bfloat16* __restrict__ Ahi, const __nv_bfloat16* __restrict__ Alo,
                      const __nv_bfloat16* __restrict__ Bhi, const __nv_bfloat16* __restrict__ Blo,
                      const float* __restrict__ bias, float* __restrict__ C,
                      int M, int N, int K, float* __restrict__ ssq)
{
    extern __shared__ char smem[];
    const uint32_t sbase = smem_u32(smem);
    const int tid  = threadIdx.x;
    const int wid  = tid >> 5;
    const int lane = tid & 31;
    const int bm = blockIdx.y * GM;
    const int bn = blockIdx.x * GN;
    const int wm = (wid >> 2) * 64;            // 0 / 64
    const int wn = (wid & 3) * 32;             // 0 / 32 / 64 / 96

    // stage loader: 4 tiles x 128 rows x 4 chunks(16B) = 2048 cp.async / 256 thr
    auto load_stage = [&](int stage, int k0) {
        const uint32_t dst0 = sbase + stage * STAGEB;
        #pragma unroll
        for (int i = 0; i < 8; ++i) {
            int id  = tid + i * 256;           // 0..2047
            int t   = id >> 9;                 // tile 0..3
            int w   = id & 511;
            int row = w >> 2;
            int c   = w & 3;
            const __nv_bfloat16* src;
            if      (t == 0) src = Ahi + (size_t)(bm + row) * K + k0 + c * 8;
            else if (t == 1) src = Alo + (size_t)(bm + row) * K + k0 + c * 8;
            else if (t == 2) src = Bhi + (size_t)(bn + row) * K + k0 + c * 8;
            else             src = Blo + (size_t)(bn + row) * K + k0 + c * 8;
            cp_async16(dst0 + t * TILEB + swz(row, c), src);
        }
        cp_commit();
    };

    float acc[4][4][4];
    #pragma unroll
    for (int i = 0; i < 4; ++i)
        #pragma unroll
        for (int j = 0; j < 4; ++j)
            #pragma unroll
            for (int q = 0; q < 4; ++q) acc[i][j][q] = 0.f;

    const int chunks = K / GK;
    load_stage(0, 0);
    load_stage(1, GK);

    // lane->tile-offset decode for ldmatrix (fixed per lane)
    const int l8  = lane & 7;
    const int sel = lane >> 3;                 // 0..3
    const int a_row = (sel & 1) * 8 + l8;
    const int a_c   = sel >> 1;
    const int b_row = (sel >> 1) * 8 + l8;
    const int b_c   = sel & 1;

    uint32_t ra[2][4], rb[2][2];
    #pragma unroll
    for (int s = 0; s < 2; ++s) {
        #pragma unroll
        for (int mi = 0; mi < 4; ++mi)
            ra[s][mi] = swz(wm + mi * 16 + a_row, 2 * s + a_c);
        #pragma unroll
        for (int jp = 0; jp < 2; ++jp)
            rb[s][jp] = swz(wn + jp * 16 + b_row, 2 * s + b_c);
    }

    int stage = 0;
    for (int ch = 0; ch < chunks; ++ch) {
        cp_wait<1>();
        __syncthreads();
        if (ch + 2 < chunks) {
            int ns = stage + 2; if (ns >= STAGES) ns -= STAGES;
            load_stage(ns, (ch + 2) * GK);
        }

        const uint32_t st = sbase + stage * STAGEB;
        const uint32_t aHiB = st + 0 * TILEB;
        const uint32_t aLoB = st + 1 * TILEB;
        const uint32_t bHiB = st + 2 * TILEB;
        const uint32_t bLoB = st + 3 * TILEB;

        #pragma unroll
        for (int s = 0; s < 2; ++s) {
            uint32_t ahi[4][4], alo[4][4], bhi[4][2], blo[4][2];
            #pragma unroll
            for (int mi = 0; mi < 4; ++mi) {
                ldmat_x4(ahi[mi], aHiB + ra[s][mi]);
                ldmat_x4(alo[mi], aLoB + ra[s][mi]);
            }
            #pragma unroll
            for (int jp = 0; jp < 2; ++jp) {
                uint32_t th[4], tl[4];
                ldmat_x4(th, bHiB + rb[s][jp]);
                ldmat_x4(tl, bLoB + rb[s][jp]);
                bhi[jp*2  ][0] = th[0]; bhi[jp*2  ][1] = th[1];
                bhi[jp*2+1][0] = th[2]; bhi[jp*2+1][1] = th[3];
                blo[jp*2  ][0] = tl[0]; blo[jp*2  ][1] = tl[1];
                blo[jp*2+1][0] = tl[2]; blo[jp*2+1][1] = tl[3];
            }
            #pragma unroll
            for (int mi = 0; mi < 4; ++mi)
                #pragma unroll
                for (int nj = 0; nj < 4; ++nj) {
                    mma_bf16(acc[mi][nj], ahi[mi], bhi[nj]);
                    mma_bf16(acc[mi][nj], alo[mi], bhi[nj]);
                    mma_bf16(acc[mi][nj], ahi[mi], blo[nj]);
                }
        }

        ++stage; if (stage >= STAGES) stage = 0;
    }

    // epilogue: frag layout row = lane/4 (+8), col = 2*(lane%4) (+1)
    const int er = lane >> 2;
    const int ec = (lane & 3) * 2;
    #pragma unroll
    for (int mi = 0; mi < 4; ++mi) {
        float pr0 = 0.f, pr1 = 0.f;
        #pragma unroll
        for (int nj = 0; nj < 4; ++nj) {
            int row0 = bm + wm + mi * 16 + er;
            int col  = bn + wn + nj * 8 + ec;
            float b0 = bias[col], b1 = bias[col + 1];
            float v00 = acc[mi][nj][0] + b0, v01 = acc[mi][nj][1] + b1;
            float v10 = acc[mi][nj][2] + b0, v11 = acc[mi][nj][3] + b1;
            *(float2*)&C[(size_t)row0 * N + col]       = make_float2(v00, v01);
            *(float2*)&C[(size_t)(row0 + 8) * N + col] = make_float2(v10, v11);
            pr0 += v00 * v00 + v01 * v01;
            pr1 += v10 * v10 + v11 * v11;
        }
        if (ssq) {
            int row0 = bm + wm + mi * 16 + er;
            #pragma unroll
            for (int o = 1; o < 4; o <<= 1) {
                pr0 += __shfl_xor_sync(0xffffffff, pr0, o);
                pr1 += __shfl_xor_sync(0xffffffff, pr1, o);
            }
            if ((lane & 3) == 0) {
                atomicAdd(&ssq[row0],     pr0);
                atomicAdd(&ssq[row0 + 8], pr1);
            }
        }
    }
}

// ---------------------------------------------------------------------------
// Elementwise kernels
// ---------------------------------------------------------------------------
// One launch: all three fp32->bf16 hi/lo splits (u, W_in, W_out); the first
// BT threads also zero the ssq accumulator (independent outputs).
#define N4_U  (BT * D_ / 4)      // 4194304
#define N4_W1 (TWOE * D_ / 4)    // 524288
#define N4_W2 (D_ * E_ / 4)      // 262144
#define N4_ALL (N4_U + N4_W1 + N4_W2)

__global__ void split_all_bf16(const float* __restrict__ u,
                               const float* __restrict__ W1,
                               const float* __restrict__ W2,
                               __nv_bfloat16* __restrict__ uhi, __nv_bfloat16* __restrict__ ulo,
                               __nv_bfloat16* __restrict__ w1hi, __nv_bfloat16* __restrict__ w1lo,
                               __nv_bfloat16* __restrict__ w2hi, __nv_bfloat16* __restrict__ w2lo,
                               float* __restrict__ ssq)
{
    int i = blockIdx.x * blockDim.x + threadIdx.x;
    if (i < BT) ssq[i] = 0.f;
    if (i >= N4_ALL) return;
    const float* src;
    __nv_bfloat16 *hi, *lo;
    int j;
    if (i < N4_U)              { src = u;  hi = uhi;  lo = ulo;  j = i; }
    else if (i < N4_U + N4_W1) { src = W1; hi = w1hi; lo = w1lo; j = i - N4_U; }
    else                       { src = W2; hi = w2hi; lo = w2lo; j = i - N4_U - N4_W1; }

    float4 v = ((const float4*)src)[j];
    __nv_bfloat16 h[4], l[4];
    float f[4] = {v.x, v.y, v.z, v.w};
    #pragma unroll
    for (int k = 0; k < 4; ++k) {
        h[k] = __float2bfloat16(f[k]);
        l[k] = __float2bfloat16(f[k] - __bfloat162float(h[k]));
    }
    ((uint2*)hi)[j] = *(uint2*)h;
    ((uint2*)lo)[j] = *(uint2*)l;
}

// conv(K=3,'same') + gate, vectorized by 4 along e; row scales inline from ssq.
__global__ void conv_gate_v4(const float* __restrict__ z1, const float* __restrict__ ssq,
                             const float* __restrict__ innw,
                             const float* __restrict__ cw, const float* __restrict__ cb,
                             __nv_bfloat16* __restrict__ ghi, __nv_bfloat16* __restrict__ glo)
{
    const int i   = blockIdx.x * blockDim.x + threadIdx.x;   // over BT*E/4
    const int g   = i & (E_ / 4 - 1);                        // float4 group in row
    const int row = i >> 8;                                  // E/4 = 256 groups/row
    const int t   = row & (T_ - 1);
    const int e   = g * 4;
    const float kinv = 1.0f / TWOE;

    const float4 wn  = *(const float4*)&innw[e];
    const float4 wnv = *(const float4*)&innw[E_ + e];
    const float4 cwa = *(const float4*)&cw[e * 3];
    const float4 cwb = *(const float4*)&cw[e * 3 + 4];
    const float4 cwc = *(const float4*)&cw[e * 3 + 8];
    const float w0[4] = {cwa.x, cwa.w, cwb.z, cwc.y};
    const float w1[4] = {cwa.y, cwb.x, cwb.w, cwc.z};
    const float w2[4] = {cwa.z, cwb.y, cwc.x, cwc.w};
    const float4 cb4 = *(const float4*)&cb[e];

    const float sc = rsqrtf(ssq[row] * kinv + EPS_);
    const float4 zc = *(const float4*)&z1[(size_t)row * TWOE + e];
    const float4 zv = *(const float4*)&z1[(size_t)row * TWOE + E_ + e];

    float xm[4] = {cb4.x, cb4.y, cb4.z, cb4.w};
    const float zcv[4] = {zc.x, zc.y, zc.z, zc.w};
    const float wnv4[4] = {wn.x, wn.y, wn.z, wn.w};

    if (t > 0) {
        const float sp = rsqrtf(ssq[row - 1] * kinv + EPS_);
        const float4 zp = *(const float4*)&z1[(size_t)(row - 1) * TWOE + e];
        const float zpv[4] = {zp.x, zp.y, zp.z, zp.w};
        #pragma unroll
        for (int k = 0; k < 4; ++k)
            xm[k] = fmaf(w0[k], zpv[k] * sp * wnv4[k], xm[k]);
    }
    #pragma unroll
    for (int k = 0; k < 4; ++k)
        xm[k] = fmaf(w1[k], zcv[k] * sc * wnv4[k], xm[k]);
    if (t < T_ - 1) {
        const float sn = rsqrtf(ssq[row + 1] * kinv + EPS_);
        const float4 zn = *(const float4*)&z1[(size_t)(row + 1) * TWOE + e];
        const float znv[4] = {zn.x, zn.y, zn.z, zn.w};
        #pragma unroll
        for (int k = 0; k < 4; ++k)
            xm[k] = fmaf(w2[k], znv[k] * sn * wnv4[k], xm[k]);
    }

    const float vv[4]  = {zv.x, zv.y, zv.z, zv.w};
    const float wv4[4] = {wnv.x, wnv.y, wnv.z, wnv.w};
    __nv_bfloat16 h[4], l[4];
    #pragma unroll
    for (int k = 0; k < 4; ++k) {
        const float gval = (vv[k] * sc * wv4[k]) * xm[k];
        h[k] = __float2bfloat16(gval);
        l[k] = __float2bfloat16(gval - __bfloat162float(h[k]));
    }
    ((uint2*)ghi)[i] = *(uint2*)h;
    ((uint2*)glo)[i] = *(uint2*)l;
}

__global__ void out_rmsnorm(float* __restrict__ out, const float* __restrict__ w)
{
    const int row = blockIdx.x;
    float4* p = (float4*)(out + (size_t)row * D_);
    float4 v = p[threadIdx.x];                  // 256 x 4 = 1024
    float acc = v.x*v.x + v.y*v.y + v.z*v.z + v.w*v.w;
    #pragma unroll
    for (int o = 16; o > 0; o >>= 1) acc += __shfl_xor_sync(0xffffffff, acc, o);
    __shared__ float warpsum[8];
    __shared__ float s_bcast;
    if ((threadIdx.x & 31) == 0) warpsum[threadIdx.x >> 5] = acc;
    __syncthreads();
    if (threadIdx.x == 0) {
        float tsum = 0.f;
        #pragma unroll
        for (int wi = 0; wi < 8; ++wi) tsum += warpsum[wi];
        s_bcast = rsqrtf(tsum * (1.0f / D_) + EPS_);
    }
    __syncthreads();
    const float s = s_bcast;
    float4 wv = *(const float4*)&w[threadIdx.x * 4];
    v.x *= s * wv.x; v.y *= s * wv.y; v.z *= s * wv.z; v.w *= s * wv.w;
    p[threadIdx.x] = v;
}

// ---------------------------------------------------------------------------
// Launch
// Inputs (metadata order): u, W_in, b_in, in_norm_w, conv_w, conv_b,
//                          W_out, b_out, out_norm_w
// ---------------------------------------------------------------------------
extern "C" void kernel_launch(void* const* d_in, const int* in_sizes, int n_in,
                              void* d_out, int out_size)
{
    const float* u      = (const float*)d_in[0];
    const float* W_in   = (const float*)d_in[1];
    const float* b_in   = (const float*)d_in[2];
    const float* innw   = (const float*)d_in[3];
    const float* conv_w = (const float*)d_in[4];
    const float* conv_b = (const float*)d_in[5];
    const float* W_out  = (const float*)d_in[6];
    const float* b_out  = (const float*)d_in[7];
    const float* outnw  = (const float*)d_in[8];
    float* out = (float*)d_out;

    float *z1, *ssq;
    __nv_bfloat16 *uhi, *ulo, *w1hi, *w1lo, *ghi, *glo, *w2hi, *w2lo;
    cudaGetSymbolAddress((void**)&z1,   g_z1);
    cudaGetSymbolAddress((void**)&ssq,  g_ssq);
    cudaGetSymbolAddress((void**)&uhi,  g_uhi);
    cudaGetSymbolAddress((void**)&ulo,  g_ulo);
    cudaGetSymbolAddress((void**)&w1hi, g_w1hi);
    cudaGetSymbolAddress((void**)&w1lo, g_w1lo);
    cudaGetSymbolAddress((void**)&ghi,  g_ghi);
    cudaGetSymbolAddress((void**)&glo,  g_glo);
    cudaGetSymbolAddress((void**)&w2hi, g_w2hi);
    cudaGetSymbolAddress((void**)&w2lo, g_w2lo);

    cudaFuncSetAttribute(gemm_hmma_bf16x2,
                         cudaFuncAttributeMaxDynamicSharedMemorySize, GEMM_SMEM);

    // 1) splits + ssq zeroing, single launch
    split_all_bf16<<<(N4_ALL + 255) / 256, 256>>>(u, W_in, W_out,
                                                  uhi, ulo, w1hi, w1lo, w2hi, w2lo,
                                                  ssq);

    // 2) in_proj GEMM (HMMA) + bias -> z1; ssq fused in epilogue
    {
        dim3 grid(TWOE / GN, BT / GM);
        gemm_hmma_bf16x2<<<grid, 256, GEMM_SMEM>>>(uhi, ulo, w1hi, w1lo, b_in, z1,
                                                   BT, TWOE, D_, ssq);
    }
    // 3) conv + gate (vectorized x4, inline row scales) -> gated bf16 hi/lo
    conv_gate_v4<<<(BT * E_ / 4) / 256, 256>>>(z1, ssq, innw, conv_w, conv_b, ghi, glo);

    // 4) out_proj GEMM + bias -> out (raw)
    {
        dim3 grid(D_ / GN, BT / GM);
        gemm_hmma_bf16x2<<<grid, 256, GEMM_SMEM>>>(ghi, glo, w2hi, w2lo, b_out, out,
                                                   BT, D_, E_, nullptr);
    }
    // 5) in-place RMSNorm on out rows
    out_rmsnorm<<<BT, 256>>>(out, outnw);
}

// round 16
// speedup vs baseline: 1.4282x; 1.3357x over previous
#include <cuda_runtime.h>
#include <cuda_fp16.h>
#include <cstdint>

// ---------------------------------------------------------------------------
// Problem constants
// ---------------------------------------------------------------------------
#define B_   4
#define T_   4096
#define D_   1024
#define E_   1024
#define TWOE 2048
#define BT   (B_ * T_)          // 16384 rows
#define EPS_ 1e-8f

// ---------------------------------------------------------------------------
// Scratch (__device__ globals; no runtime allocation allowed)
// ---------------------------------------------------------------------------
__device__ float  g_z1[(size_t)BT * TWOE];     // in_proj pre-norm (fp32)
__device__ float  g_ssq[BT];                   // row sum-of-squares
__device__ __half g_uhi[(size_t)BT * D_];      // u split hi (fp16)
__device__ __half g_ulo[(size_t)BT * D_];      // u split lo (fp16)
__device__ __half g_w1h[(size_t)TWOE * D_];    // W_in rounded fp16
__device__ __half g_ghi[(size_t)BT * E_];      // gated split hi
__device__ __half g_glo[(size_t)BT * E_];      // gated split lo
__device__ __half g_w2h[(size_t)D_ * E_];      // W_out rounded fp16

// ---------------------------------------------------------------------------
// HMMA fp16 2-term GEMM (NT): C[m,n] = sum_k A[m,k]*Bh[n,k] + bias[n]
//   A = Ahi + Alo (exact fp16 split), Bh = fp16(B). C = Ahi*Bh + Alo*Bh.
//   Error = A*(B - Bh) ~ 2^-12 relative -> well under 1e-3 after 2 stages.
// 128x128 CTA tile, GK=32 (two k16 steps per barrier), 8 warps (64x32 warp
// tile), 3-stage cp.async circular pipeline (wait_group 1, one barrier per
// chunk), 72KB dynamic smem, 2 CTAs/SM.  [pipeline = R10/R14 measured optimum]
// Swizzle (64B rows): row r, 16B chunk c -> r*64 + ((c ^ ((r>>1)&3)) * 16).
// Optional: epilogue atomically accumulates per-row sum(C^2) into ssq.
// ---------------------------------------------------------------------------
#define GM 128
#define GN 128
#define GK 32
#define ROWB 64                   // bytes per smem row (32 fp16)
#define TILEB (128 * ROWB)        // 8192 B per tile
#define STAGEB (3 * TILEB)        // 24576 B (Ahi, Alo, Bh)
#define STAGES 3
#define GEMM_SMEM (STAGES * STAGEB)   // 73728 B

#define OFF_ALO (TILEB)
#define OFF_BH  (2 * TILEB)

__device__ __forceinline__ uint32_t smem_u32(const void* p) {
    uint32_t a;
    asm("{ .reg .u64 t; cvta.to.shared.u64 t, %1; cvt.u32.u64 %0, t; }" : "=r"(a) : "l"(p));
    return a;
}
__device__ __forceinline__ void cp_async16(uint32_t dst, const void* src) {
    asm volatile("cp.async.cg.shared.global [%0], [%1], 16;\n" :: "r"(dst), "l"(src));
}
__device__ __forceinline__ void cp_commit() { asm volatile("cp.async.commit_group;\n"); }
template <int N>
__device__ __forceinline__ void cp_wait() { asm volatile("cp.async.wait_group %0;\n" :: "n"(N)); }

__device__ __forceinline__ void ldmat_x4(uint32_t* r, uint32_t addr) {
    asm volatile("ldmatrix.sync.aligned.m8n8.x4.shared.b16 {%0,%1,%2,%3}, [%4];"
                 : "=r"(r[0]), "=r"(r[1]), "=r"(r[2]), "=r"(r[3]) : "r"(addr));
}
__device__ __forceinline__ void mma_f16(float* d, const uint32_t* a, const uint32_t* b) {
    asm volatile(
        "mma.sync.aligned.m16n8k16.row.col.f32.f16.f16.f32 "
        "{%0,%1,%2,%3}, {%4,%5,%6,%7}, {%8,%9}, {%0,%1,%2,%3};"
        : "+f"(d[0]), "+f"(d[1]), "+f"(d[2]), "+f"(d[3])
        : "r"(a[0]), "r"(a[1]), "r"(a[2]), "r"(a[3]), "r"(b[0]), "r"(b[1]));
}

// swizzled byte offset within one 128x32 tile for (row, 16B-chunk 0..3)
__device__ __forceinline__ uint32_t swz(int row, int c16) {
    return (uint32_t)(row * ROWB + ((c16 ^ ((row >> 1) & 3)) * 16));
}

__global__ __launch_bounds__(256, 2)
void gemm_hmma_f16x2(const __half* __restrict__ Ahi, const __half* __restrict__ Alo,
                     const __half* __restrict__ Bh,
                     const float* __restrict__ bias, float* __restrict__ C,
                     int M, int N, int K, float* __restrict__ ssq)
{
    extern __shared__ char smem[];
    const uint32_t sbase = smem_u32(smem);
    const int tid  = threadIdx.x;
    const int wid  = tid >> 5;
    const int lane = tid & 31;
    const int bm = blockIdx.y * GM;
    const int bn = blockIdx.x * GN;
    const int wm = (wid >> 2) * 64;            // 0 / 64
    const int wn = (wid & 3) * 32;             // 0 / 32 / 64 / 96

    // stage loader: 3 tiles x 128 rows x 4 chunks(16B) = 1536 cp.async / 256 thr
    auto load_stage = [&](int stage, int k0) {
        const uint32_t dst0 = sbase + stage * STAGEB;
        #pragma unroll
        for (int i = 0; i < 6; ++i) {
            int id  = tid + i * 256;           // 0..1535
            int t   = id >> 9;                 // tile 0..2
            int w   = id & 511;
            int row = w >> 2;
            int c   = w & 3;
            const __half* src;
            if      (t == 0) src = Ahi + (size_t)(bm + row) * K + k0 + c * 8;
            else if (t == 1) src = Alo + (size_t)(bm + row) * K + k0 + c * 8;
            else             src = Bh  + (size_t)(bn + row) * K + k0 + c * 8;
            cp_async16(dst0 + t * TILEB + swz(row, c), src);
        }
        cp_commit();
    };

    float acc[4][4][4];
    #pragma unroll
    for (int i = 0; i < 4; ++i)
        #pragma unroll
        for (int j = 0; j < 4; ++j)
            #pragma unroll
            for (int q = 0; q < 4; ++q) acc[i][j][q] = 0.f;

    const int chunks = K / GK;
    load_stage(0, 0);
    load_stage(1, GK);

    // lane->tile-offset decode for ldmatrix (fixed per lane)
    const int l8  = lane & 7;
    const int sel = lane >> 3;                 // 0..3
    const int a_row = (sel & 1) * 8 + l8;
    const int a_c   = sel >> 1;
    const int b_row = (sel >> 1) * 8 + l8;
    const int b_c   = sel & 1;

    uint32_t ra[2][4], rb[2][2];
    #pragma unroll
    for (int s = 0; s < 2; ++s) {
        #pragma unroll
        for (int mi = 0; mi < 4; ++mi)
            ra[s][mi] = swz(wm + mi * 16 + a_row, 2 * s + a_c);
        #pragma unroll
        for (int jp = 0; jp < 2; ++jp)
            rb[s][jp] = swz(wn + jp * 16 + b_row, 2 * s + b_c);
    }

    int stage = 0;
    for (int ch = 0; ch < chunks; ++ch) {
        cp_wait<1>();
        __syncthreads();
        if (ch + 2 < chunks) {
            int ns = stage + 2; if (ns >= STAGES) ns -= STAGES;
            load_stage(ns, (ch + 2) * GK);
        }

        const uint32_t st = sbase + stage * STAGEB;
        const uint32_t aHiB = st;
        const uint32_t aLoB = st + OFF_ALO;
        const uint32_t bHB  = st + OFF_BH;

        #pragma unroll
        for (int s = 0; s < 2; ++s) {
            uint32_t ahi[4][4], alo[4][4], bh[4][2];
            #pragma unroll
            for (int mi = 0; mi < 4; ++mi) {
                ldmat_x4(ahi[mi], aHiB + ra[s][mi]);
                ldmat_x4(alo[mi], aLoB + ra[s][mi]);
            }
            #pragma unroll
            for (int jp = 0; jp < 2; ++jp) {
                uint32_t th[4];
                ldmat_x4(th, bHB + rb[s][jp]);
                bh[jp*2  ][0] = th[0]; bh[jp*2  ][1] = th[1];
                bh[jp*2+1][0] = th[2]; bh[jp*2+1][1] = th[3];
            }
            #pragma unroll
            for (int mi = 0; mi < 4; ++mi)
                #pragma unroll
                for (int nj = 0; nj < 4; ++nj) {
                    mma_f16(acc[mi][nj], ahi[mi], bh[nj]);
                    mma_f16(acc[mi][nj], alo[mi], bh[nj]);
                }
        }

        ++stage; if (stage >= STAGES) stage = 0;
    }

    // epilogue: frag layout row = lane/4 (+8), col = 2*(lane%4) (+1)
    const int er = lane >> 2;
    const int ec = (lane & 3) * 2;
    #pragma unroll
    for (int mi = 0; mi < 4; ++mi) {
        float pr0 = 0.f, pr1 = 0.f;
        #pragma unroll
        for (int nj = 0; nj < 4; ++nj) {
            int row0 = bm + wm + mi * 16 + er;
            int col  = bn + wn + nj * 8 + ec;
            float b0 = bias[col], b1 = bias[col + 1];
            float v00 = acc[mi][nj][0] + b0, v01 = acc[mi][nj][1] + b1;
            float v10 = acc[mi][nj][2] + b0, v11 = acc[mi][nj][3] + b1;
            *(float2*)&C[(size_t)row0 * N + col]       = make_float2(v00, v01);
            *(float2*)&C[(size_t)(row0 + 8) * N + col] = make_float2(v10, v11);
            pr0 += v00 * v00 + v01 * v01;
            pr1 += v10 * v10 + v11 * v11;
        }
        if (ssq) {
            int row0 = bm + wm + mi * 16 + er;
            #pragma unroll
            for (int o = 1; o < 4; o <<= 1) {
                pr0 += __shfl_xor_sync(0xffffffff, pr0, o);
                pr1 += __shfl_xor_sync(0xffffffff, pr1, o);
            }
            if ((lane & 3) == 0) {
                atomicAdd(&ssq[row0],     pr0);
                atomicAdd(&ssq[row0 + 8], pr1);
            }
        }
    }
}

// ---------------------------------------------------------------------------
// Elementwise kernels
// ---------------------------------------------------------------------------
// One launch: u -> fp16 hi/lo split; W_in, W_out -> rounded fp16.
// First BT threads also zero the ssq accumulator.
#define N4_U  (BT * D_ / 4)      // 4194304
#define N4_W1 (TWOE * D_ / 4)    // 524288
#define N4_W2 (D_ * E_ / 4)      // 262144
#define N4_ALL (N4_U + N4_W1 + N4_W2)

__global__ void split_all_f16(const float* __restrict__ u,
                              const float* __restrict__ W1,
                              const float* __restrict__ W2,
                              __half* __restrict__ uhi, __half* __restrict__ ulo,
                              __half* __restrict__ w1h, __half* __restrict__ w2h,
                              float* __restrict__ ssq)
{
    int i = blockIdx.x * blockDim.x + threadIdx.x;
    if (i < BT) ssq[i] = 0.f;
    if (i >= N4_ALL) return;
    if (i < N4_U) {
        float4 v = ((const float4*)u)[i];
        __half h[4], l[4];
        float f[4] = {v.x, v.y, v.z, v.w};
        #pragma unroll
        for (int k = 0; k < 4; ++k) {
            h[k] = __float2half(f[k]);
            l[k] = __float2half(f[k] - __half2float(h[k]));
        }
        ((uint2*)uhi)[i] = *(uint2*)h;
        ((uint2*)ulo)[i] = *(uint2*)l;
    } else {
        const float* src;
        __half* dst;
        int j;
        if (i < N4_U + N4_W1) { src = W1; dst = w1h; j = i - N4_U; }
        else                  { src = W2; dst = w2h; j = i - N4_U - N4_W1; }
        float4 v = ((const float4*)src)[j];
        __half h[4];
        h[0] = __float2half(v.x); h[1] = __float2half(v.y);
        h[2] = __float2half(v.z); h[3] = __float2half(v.w);
        ((uint2*)dst)[j] = *(uint2*)h;
    }
}

// conv(K=3,'same') + gate, vectorized by 4 along e; row scales inline from ssq.
// Writes gated as exact fp16 hi/lo split.
__global__ void conv_gate_v4(const float* __restrict__ z1, const float* __restrict__ ssq,
                             const float* __restrict__ innw,
                             const float* __restrict__ cw, const float* __restrict__ cb,
                             __half* __restrict__ ghi, __half* __restrict__ glo)
{
    const int i   = blockIdx.x * blockDim.x + threadIdx.x;   // over BT*E/4
    const int g   = i & (E_ / 4 - 1);                        // float4 group in row
    const int row = i >> 8;                                  // E/4 = 256 groups/row
    const int t   = row & (T_ - 1);
    const int e   = g * 4;
    const float kinv = 1.0f / TWOE;

    const float4 wn  = *(const float4*)&innw[e];
    const float4 wnv = *(const float4*)&innw[E_ + e];
    const float4 cwa = *(const float4*)&cw[e * 3];
    const float4 cwb = *(const float4*)&cw[e * 3 + 4];
    const float4 cwc = *(const float4*)&cw[e * 3 + 8];
    const float w0[4] = {cwa.x, cwa.w, cwb.z, cwc.y};
    const float w1[4] = {cwa.y, cwb.x, cwb.w, cwc.z};
    const float w2[4] = {cwa.z, cwb.y, cwc.x, cwc.w};
    const float4 cb4 = *(const float4*)&cb[e];

    const float sc = rsqrtf(ssq[row] * kinv + EPS_);
    const float4 zc = *(const float4*)&z1[(size_t)row * TWOE + e];
    const float4 zv = *(const float4*)&z1[(size_t)row * TWOE + E_ + e];

    float xm[4] = {cb4.x, cb4.y, cb4.z, cb4.w};
    const float zcv[4] = {zc.x, zc.y, zc.z, zc.w};
    const float wnv4[4] = {wn.x, wn.y, wn.z, wn.w};

    if (t > 0) {
        const float sp = rsqrtf(ssq[row - 1] * kinv + EPS_);
        const float4 zp = *(const float4*)&z1[(size_t)(row - 1) * TWOE + e];
        const float zpv[4] = {zp.x, zp.y, zp.z, zp.w};
        #pragma unroll
        for (int k = 0; k < 4; ++k)
            xm[k] = fmaf(w0[k], zpv[k] * sp * wnv4[k], xm[k]);
    }
    #pragma unroll
    for (int k = 0; k < 4; ++k)
        xm[k] = fmaf(w1[k], zcv[k] * sc * wnv4[k], xm[k]);
    if (t < T_ - 1) {
        const float sn = rsqrtf(ssq[row + 1] * kinv + EPS_);
        const float4 zn = *(const float4*)&z1[(size_t)(row + 1) * TWOE + e];
        const float znv[4] = {zn.x, zn.y, zn.z, zn.w};
        #pragma unroll
        for (int k = 0; k < 4; ++k)
            xm[k] = fmaf(w2[k], znv[k] * sn * wnv4[k], xm[k]);
    }

    const float vv[4]  = {zv.x, zv.y, zv.z, zv.w};
    const float wv4[4] = {wnv.x, wnv.y, wnv.z, wnv.w};
    __half h[4], l[4];
    #pragma unroll
    for (int k = 0; k < 4; ++k) {
        const float gval = (vv[k] * sc * wv4[k]) * xm[k];
        h[k] = __float2half(gval);
        l[k] = __float2half(gval - __half2float(h[k]));
    }
    ((uint2*)ghi)[i] = *(uint2*)h;
    ((uint2*)glo)[i] = *(uint2*)l;
}

__global__ void out_rmsnorm(float* __restrict__ out, const float* __restrict__ w)
{
    const int row = blockIdx.x;
    float4* p = (float4*)(out + (size_t)row * D_);
    float4 v = p[threadIdx.x];                  // 256 x 4 = 1024
    float acc = v.x*v.x + v.y*v.y + v.z*v.z + v.w*v.w;
    #pragma unroll
    for (int o = 16; o > 0; o >>= 1) acc += __shfl_xor_sync(0xffffffff, acc, o);
    __shared__ float warpsum[8];
    __shared__ float s_bcast;
    if ((threadIdx.x & 31) == 0) warpsum[threadIdx.x >> 5] = acc;
    __syncthreads();
    if (threadIdx.x == 0) {
        float tsum = 0.f;
        #pragma unroll
        for (int wi = 0; wi < 8; ++wi) tsum += warpsum[wi];
        s_bcast = rsqrtf(tsum * (1.0f / D_) + EPS_);
    }
    __syncthreads();
    const float s = s_bcast;
    float4 wv = *(const float4*)&w[threadIdx.x * 4];
    v.x *= s * wv.x; v.y *= s * wv.y; v.z *= s * wv.z; v.w *= s * wv.w;
    p[threadIdx.x] = v;
}

// ---------------------------------------------------------------------------
// Launch
// Inputs (metadata order): u, W_in, b_in, in_norm_w, conv_w, conv_b,
//                          W_out, b_out, out_norm_w
// ---------------------------------------------------------------------------
extern "C" void kernel_launch(void* const* d_in, const int* in_sizes, int n_in,
                              void* d_out, int out_size)
{
    const float* u      = (const float*)d_in[0];
    const float* W_in   = (const float*)d_in[1];
    const float* b_in   = (const float*)d_in[2];
    const float* innw   = (const float*)d_in[3];
    const float* conv_w = (const float*)d_in[4];
    const float* conv_b = (const float*)d_in[5];
    const float* W_out  = (const float*)d_in[6];
    const float* b_out  = (const float*)d_in[7];
    const float* outnw  = (const float*)d_in[8];
    float* out = (float*)d_out;

    float *z1, *ssq;
    __half *uhi, *ulo, *w1h, *ghi, *glo, *w2h;
    cudaGetSymbolAddress((void**)&z1,  g_z1);
    cudaGetSymbolAddress((void**)&ssq, g_ssq);
    cudaGetSymbolAddress((void**)&uhi, g_uhi);
    cudaGetSymbolAddress((void**)&ulo, g_ulo);
    cudaGetSymbolAddress((void**)&w1h, g_w1h);
    cudaGetSymbolAddress((void**)&ghi, g_ghi);
    cudaGetSymbolAddress((void**)&glo, g_glo);
    cudaGetSymbolAddress((void**)&w2h, g_w2h);

    cudaFuncSetAttribute(gemm_hmma_f16x2,
                         cudaFuncAttributeMaxDynamicSharedMemorySize, GEMM_SMEM);

    // 1) splits + ssq zeroing, single launch
    split_all_f16<<<(N4_ALL + 255) / 256, 256>>>(u, W_in, W_out,
                                                 uhi, ulo, w1h, w2h, ssq);

    // 2) in_proj GEMM (HMMA fp16 2-term) + bias -> z1; ssq fused in epilogue
    {
        dim3 grid(TWOE / GN, BT / GM);
        gemm_hmma_f16x2<<<grid, 256, GEMM_SMEM>>>(uhi, ulo, w1h, b_in, z1,
                                                  BT, TWOE, D_, ssq);
    }
    // 3) conv + gate (vectorized x4, inline row scales) -> gated fp16 hi/lo
    conv_gate_v4<<<(BT * E_ / 4) / 256, 256>>>(z1, ssq, innw, conv_w, conv_b, ghi, glo);

    // 4) out_proj GEMM + bias -> out (raw)
    {
        dim3 grid(D_ / GN, BT / GM);
        gemm_hmma_f16x2<<<grid, 256, GEMM_SMEM>>>(ghi, glo, w2h, b_out, out,
                                                  BT, D_, E_, nullptr);
    }
    // 5) in-place RMSNorm on out rows
    out_rmsnorm<<<BT, 256>>>(out, outnw);
}

// round 17
// speedup vs baseline: 1.4353x; 1.0050x over previous
#include <cuda_runtime.h>
#include <cuda_fp16.h>
#include <cstdint>

// ---------------------------------------------------------------------------
// Problem constants
// ---------------------------------------------------------------------------
#define B_   4
#define T_   4096
#define D_   1024
#define E_   1024
#define TWOE 2048
#define BT   (B_ * T_)          // 16384 rows
#define EPS_ 1e-8f

// ---------------------------------------------------------------------------
// Scratch (__device__ globals; no runtime allocation allowed)
// ---------------------------------------------------------------------------
__device__ float  g_z1[(size_t)BT * TWOE];     // in_proj pre-norm (fp32)
__device__ float  g_ssq[BT];                   // row sum-of-squares
__device__ __half g_uhi[(size_t)BT * D_];      // u split hi (fp16)
__device__ __half g_ulo[(size_t)BT * D_];      // u split lo (fp16)
__device__ __half g_w1h[(size_t)TWOE * D_];    // W_in rounded fp16
__device__ __half g_ghi[(size_t)BT * E_];      // gated split hi
__device__ __half g_glo[(size_t)BT * E_];      // gated split lo
__device__ __half g_w2h[(size_t)D_ * E_];      // W_out rounded fp16

// ---------------------------------------------------------------------------
// HMMA fp16 2-term GEMM (NT): C[m,n] = sum_k A[m,k]*Bh[n,k] + bias[n]
//   A = Ahi + Alo (exact fp16 split), Bh = fp16(B). C = Ahi*Bh + Alo*Bh.
// 128x128 CTA tile, GK=32 (two k16 steps per barrier), 8 warps (64x32 warp
// tile), 4-stage cp.async circular pipeline (wait_group 2 -> ~2.5-chunk
// prefetch distance), 96KB dynamic smem, 2 CTAs/SM.
// Swizzle (64B rows): row r, 16B chunk c -> r*64 + ((c ^ ((r>>1)&3)) * 16).
// Optional: epilogue atomically accumulates per-row sum(C^2) into ssq.
// ---------------------------------------------------------------------------
#define GM 128
#define GN 128
#define GK 32
#define ROWB 64                   // bytes per smem row (32 fp16)
#define TILEB (128 * ROWB)        // 8192 B per tile
#define STAGEB (3 * TILEB)        // 24576 B (Ahi, Alo, Bh)
#define STAGES 4
#define GEMM_SMEM (STAGES * STAGEB)   // 98304 B

#define OFF_ALO (TILEB)
#define OFF_BH  (2 * TILEB)

__device__ __forceinline__ uint32_t smem_u32(const void* p) {
    uint32_t a;
    asm("{ .reg .u64 t; cvta.to.shared.u64 t, %1; cvt.u32.u64 %0, t; }" : "=r"(a) : "l"(p));
    return a;
}
__device__ __forceinline__ void cp_async16(uint32_t dst, const void* src) {
    asm volatile("cp.async.cg.shared.global [%0], [%1], 16;\n" :: "r"(dst), "l"(src));
}
__device__ __forceinline__ void cp_commit() { asm volatile("cp.async.commit_group;\n"); }
template <int N>
__device__ __forceinline__ void cp_wait() { asm volatile("cp.async.wait_group %0;\n" :: "n"(N)); }

__device__ __forceinline__ void ldmat_x4(uint32_t* r, uint32_t addr) {
    asm volatile("ldmatrix.sync.aligned.m8n8.x4.shared.b16 {%0,%1,%2,%3}, [%4];"
                 : "=r"(r[0]), "=r"(r[1]), "=r"(r[2]), "=r"(r[3]) : "r"(addr));
}
__device__ __forceinline__ void mma_f16(float* d, const uint32_t* a, const uint32_t* b) {
    asm volatile(
        "mma.sync.aligned.m16n8k16.row.col.f32.f16.f16.f32 "
        "{%0,%1,%2,%3}, {%4,%5,%6,%7}, {%8,%9}, {%0,%1,%2,%3};"
        : "+f"(d[0]), "+f"(d[1]), "+f"(d[2]), "+f"(d[3])
        : "r"(a[0]), "r"(a[1]), "r"(a[2]), "r"(a[3]), "r"(b[0]), "r"(b[1]));
}

// swizzled byte offset within one 128x32 tile for (row, 16B-chunk 0..3)
__device__ __forceinline__ uint32_t swz(int row, int c16) {
    return (uint32_t)(row * ROWB + ((c16 ^ ((row >> 1) & 3)) * 16));
}

__global__ __launch_bounds__(256, 2)
void gemm_hmma_f16x2(const __half* __restrict__ Ahi, const __half* __restrict__ Alo,
                     const __half* __restrict__ Bh,
                     const float* __restrict__ bias, float* __restrict__ C,
                     int M, int N, int K, float* __restrict__ ssq)
{
    extern __shared__ char smem[];
    const uint32_t sbase = smem_u32(smem);
    const int tid  = threadIdx.x;
    const int wid  = tid >> 5;
    const int lane = tid & 31;
    const int bm = blockIdx.y * GM;
    const int bn = blockIdx.x * GN;
    const int wm = (wid >> 2) * 64;            // 0 / 64
    const int wn = (wid & 3) * 32;             // 0 / 32 / 64 / 96

    // stage loader: 3 tiles x 128 rows x 4 chunks(16B) = 1536 cp.async / 256 thr
    auto load_stage = [&](int stage, int k0) {
        const uint32_t dst0 = sbase + stage * STAGEB;
        #pragma unroll
        for (int i = 0; i < 6; ++i) {
            int id  = tid + i * 256;           // 0..1535
            int t   = id >> 9;                 // tile 0..2
            int w   = id & 511;
            int row = w >> 2;
            int c   = w & 3;
            const __half* src;
            if      (t == 0) src = Ahi + (size_t)(bm + row) * K + k0 + c * 8;
            else if (t == 1) src = Alo + (size_t)(bm + row) * K + k0 + c * 8;
            else             src = Bh  + (size_t)(bn + row) * K + k0 + c * 8;
            cp_async16(dst0 + t * TILEB + swz(row, c), src);
        }
        cp_commit();
    };

    float acc[4][4][4];
    #pragma unroll
    for (int i = 0; i < 4; ++i)
        #pragma unroll
        for (int j = 0; j < 4; ++j)
            #pragma unroll
            for (int q = 0; q < 4; ++q) acc[i][j][q] = 0.f;

    const int chunks = K / GK;
    load_stage(0, 0);
    load_stage(1, GK);
    load_stage(2, 2 * GK);

    // lane->tile-offset decode for ldmatrix (fixed per lane)
    const int l8  = lane & 7;
    const int sel = lane >> 3;                 // 0..3
    const int a_row = (sel & 1) * 8 + l8;
    const int a_c   = sel >> 1;
    const int b_row = (sel >> 1) * 8 + l8;
    const int b_c   = sel & 1;

    uint32_t ra[2][4], rb[2][2];
    #pragma unroll
    for (int s = 0; s < 2; ++s) {
        #pragma unroll
        for (int mi = 0; mi < 4; ++mi)
            ra[s][mi] = swz(wm + mi * 16 + a_row, 2 * s + a_c);
        #pragma unroll
        for (int jp = 0; jp < 2; ++jp)
            rb[s][jp] = swz(wn + jp * 16 + b_row, 2 * s + b_c);
    }

    int stage = 0;
    for (int ch = 0; ch < chunks; ++ch) {
        cp_wait<2>();                           // current stage landed (3 groups max in flight)
        __syncthreads();                        // visible; oldest buffer consumed
        if (ch + 3 < chunks) {
            int ns = stage + 3; if (ns >= STAGES) ns -= STAGES;
            load_stage(ns, (ch + 3) * GK);      // overwrites buffer consumed at ch-1
        }

        const uint32_t st = sbase + stage * STAGEB;
        const uint32_t aHiB = st;
        const uint32_t aLoB = st + OFF_ALO;
        const uint32_t bHB  = st + OFF_BH;

        #pragma unroll
        for (int s = 0; s < 2; ++s) {
            uint32_t ahi[4][4], alo[4][4], bh[4][2];
            #pragma unroll
            for (int mi = 0; mi < 4; ++mi) {
                ldmat_x4(ahi[mi], aHiB + ra[s][mi]);
                ldmat_x4(alo[mi], aLoB + ra[s][mi]);
            }
            #pragma unroll
            for (int jp = 0; jp < 2; ++jp) {
                uint32_t th[4];
                ldmat_x4(th, bHB + rb[s][jp]);
                bh[jp*2  ][0] = th[0]; bh[jp*2  ][1] = th[1];
                bh[jp*2+1][0] = th[2]; bh[jp*2+1][1] = th[3];
            }
            #pragma unroll
            for (int mi = 0; mi < 4; ++mi)
                #pragma unroll
                for (int nj = 0; nj < 4; ++nj) {
                    mma_f16(acc[mi][nj], ahi[mi], bh[nj]);
                    mma_f16(acc[mi][nj], alo[mi], bh[nj]);
                }
        }

        ++stage; if (stage >= STAGES) stage = 0;
    }

    // epilogue: frag layout row = lane/4 (+8), col = 2*(lane%4) (+1)
    const int er = lane >> 2;
    const int ec = (lane & 3) * 2;
    #pragma unroll
    for (int mi = 0; mi < 4; ++mi) {
        float pr0 = 0.f, pr1 = 0.f;
        #pragma unroll
        for (int nj = 0; nj < 4; ++nj) {
            int row0 = bm + wm + mi * 16 + er;
            int col  = bn + wn + nj * 8 + ec;
            float b0 = bias[col], b1 = bias[col + 1];
            float v00 = acc[mi][nj][0] + b0, v01 = acc[mi][nj][1] + b1;
            float v10 = acc[mi][nj][2] + b0, v11 = acc[mi][nj][3] + b1;
            *(float2*)&C[(size_t)row0 * N + col]       = make_float2(v00, v01);
            *(float2*)&C[(size_t)(row0 + 8) * N + col] = make_float2(v10, v11);
            pr0 += v00 * v00 + v01 * v01;
            pr1 += v10 * v10 + v11 * v11;
        }
        if (ssq) {
            int row0 = bm + wm + mi * 16 + er;
            #pragma unroll
            for (int o = 1; o < 4; o <<= 1) {
                pr0 += __shfl_xor_sync(0xffffffff, pr0, o);
                pr1 += __shfl_xor_sync(0xffffffff, pr1, o);
            }
            if ((lane & 3) == 0) {
                atomicAdd(&ssq[row0],     pr0);
                atomicAdd(&ssq[row0 + 8], pr1);
            }
        }
    }
}

// ---------------------------------------------------------------------------
// Elementwise kernels
// ---------------------------------------------------------------------------
// One launch: u -> fp16 hi/lo split; W_in, W_out -> rounded fp16.
// First BT threads also zero the ssq accumulator.
#define N4_U  (BT * D_ / 4)      // 4194304
#define N4_W1 (TWOE * D_ / 4)    // 524288
#define N4_W2 (D_ * E_ / 4)      // 262144
#define N4_ALL (N4_U + N4_W1 + N4_W2)

__global__ void split_all_f16(const float* __restrict__ u,
                              const float* __restrict__ W1,
                              const float* __restrict__ W2,
                              __half* __restrict__ uhi, __half* __restrict__ ulo,
                              __half* __restrict__ w1h, __half* __restrict__ w2h,
                              float* __restrict__ ssq)
{
    int i = blockIdx.x * blockDim.x + threadIdx.x;
    if (i < BT) ssq[i] = 0.f;
    if (i >= N4_ALL) return;
    if (i < N4_U) {
        float4 v = ((const float4*)u)[i];
        __half h[4], l[4];
        float f[4] = {v.x, v.y, v.z, v.w};
        #pragma unroll
        for (int k = 0; k < 4; ++k) {
            h[k] = __float2half(f[k]);
            l[k] = __float2half(f[k] - __half2float(h[k]));
        }
        ((uint2*)uhi)[i] = *(uint2*)h;
        ((uint2*)ulo)[i] = *(uint2*)l;
    } else {
        const float* src;
        __half* dst;
        int j;
        if (i < N4_U + N4_W1) { src = W1; dst = w1h; j = i - N4_U; }
        else                  { src = W2; dst = w2h; j = i - N4_U - N4_W1; }
        float4 v = ((const float4*)src)[j];
        __half h[4];
        h[0] = __float2half(v.x); h[1] = __float2half(v.y);
        h[2] = __float2half(v.z); h[3] = __float2half(v.w);
        ((uint2*)dst)[j] = *(uint2*)h;
    }
}

// conv(K=3,'same') + gate, vectorized by 4 along e; row scales inline from ssq.
// Writes gated as exact fp16 hi/lo split.
__global__ void conv_gate_v4(const float* __restrict__ z1, const float* __restrict__ ssq,
                             const float* __restrict__ innw,
                             const float* __restrict__ cw, const float* __restrict__ cb,
                             __half* __restrict__ ghi, __half* __restrict__ glo)
{
    const int i   = blockIdx.x * blockDim.x + threadIdx.x;   // over BT*E/4
    const int g   = i & (E_ / 4 - 1);                        // float4 group in row
    const int row = i >> 8;                                  // E/4 = 256 groups/row
    const int t   = row & (T_ - 1);
    const int e   = g * 4;
    const float kinv = 1.0f / TWOE;

    const float4 wn  = *(const float4*)&innw[e];
    const float4 wnv = *(const float4*)&innw[E_ + e];
    const float4 cwa = *(const float4*)&cw[e * 3];
    const float4 cwb = *(const float4*)&cw[e * 3 + 4];
    const float4 cwc = *(const float4*)&cw[e * 3 + 8];
    const float w0[4] = {cwa.x, cwa.w, cwb.z, cwc.y};
    const float w1[4] = {cwa.y, cwb.x, cwb.w, cwc.z};
    const float w2[4] = {cwa.z, cwb.y, cwc.x, cwc.w};
    const float4 cb4 = *(const float4*)&cb[e];

    const float sc = rsqrtf(ssq[row] * kinv + EPS_);
    const float4 zc = *(const float4*)&z1[(size_t)row * TWOE + e];
    const float4 zv = *(const float4*)&z1[(size_t)row * TWOE + E_ + e];

    float xm[4] = {cb4.x, cb4.y, cb4.z, cb4.w};
    const float zcv[4] = {zc.x, zc.y, zc.z, zc.w};
    const float wnv4[4] = {wn.x, wn.y, wn.z, wn.w};

    if (t > 0) {
        const float sp = rsqrtf(ssq[row - 1] * kinv + EPS_);
        const float4 zp = *(const float4*)&z1[(size_t)(row - 1) * TWOE + e];
        const float zpv[4] = {zp.x, zp.y, zp.z, zp.w};
        #pragma unroll
        for (int k = 0; k < 4; ++k)
            xm[k] = fmaf(w0[k], zpv[k] * sp * wnv4[k], xm[k]);
    }
    #pragma unroll
    for (int k = 0; k < 4; ++k)
        xm[k] = fmaf(w1[k], zcv[k] * sc * wnv4[k], xm[k]);
    if (t < T_ - 1) {
        const float sn = rsqrtf(ssq[row + 1] * kinv + EPS_);
        const float4 zn = *(const float4*)&z1[(size_t)(row + 1) * TWOE + e];
        const float znv[4] = {zn.x, zn.y, zn.z, zn.w};
        #pragma unroll
        for (int k = 0; k < 4; ++k)
            xm[k] = fmaf(w2[k], znv[k] * sn * wnv4[k], xm[k]);
    }

    const float vv[4]  = {zv.x, zv.y, zv.z, zv.w};
    const float wv4[4] = {wnv.x, wnv.y, wnv.z, wnv.w};
    __half h[4], l[4];
    #pragma unroll
    for (int k = 0; k < 4; ++k) {
        const float gval = (vv[k] * sc * wv4[k]) * xm[k];
        h[k] = __float2half(gval);
        l[k] = __float2half(gval - __half2float(h[k]));
    }
    ((uint2*)ghi)[i] = *(uint2*)h;
    ((uint2*)glo)[i] = *(uint2*)l;
}

__global__ void out_rmsnorm(float* __restrict__ out, const float* __restrict__ w)
{
    const int row = blockIdx.x;
    float4* p = (float4*)(out + (size_t)row * D_);
    float4 v = p[threadIdx.x];                  // 256 x 4 = 1024
    float acc = v.x*v.x + v.y*v.y + v.z*v.z + v.w*v.w;
    #pragma unroll
    for (int o = 16; o > 0; o >>= 1) acc += __shfl_xor_sync(0xffffffff, acc, o);
    __shared__ float warpsum[8];
    __shared__ float s_bcast;
    if ((threadIdx.x & 31) == 0) warpsum[threadIdx.x >> 5] = acc;
    __syncthreads();
    if (threadIdx.x == 0) {
        float tsum = 0.f;
        #pragma unroll
        for (int wi = 0; wi < 8; ++wi) tsum += warpsum[wi];
        s_bcast = rsqrtf(tsum * (1.0f / D_) + EPS_);
    }
    __syncthreads();
    const float s = s_bcast;
    float4 wv = *(const float4*)&w[threadIdx.x * 4];
    v.x *= s * wv.x; v.y *= s * wv.y; v.z *= s * wv.z; v.w *= s * wv.w;
    p[threadIdx.x] = v;
}

// ---------------------------------------------------------------------------
// Launch
// Inputs (metadata order): u, W_in, b_in, in_norm_w, conv_w, conv_b,
//                          W_out, b_out, out_norm_w
// ---------------------------------------------------------------------------
extern "C" void kernel_launch(void* const* d_in, const int* in_sizes, int n_in,
                              void* d_out, int out_size)
{
    const float* u      = (const float*)d_in[0];
    const float* W_in   = (const float*)d_in[1];
    const float* b_in   = (const float*)d_in[2];
    const float* innw   = (const float*)d_in[3];
    const float* conv_w = (const float*)d_in[4];
    const float* conv_b = (const float*)d_in[5];
    const float* W_out  = (const float*)d_in[6];
    const float* b_out  = (const float*)d_in[7];
    const float* outnw  = (const float*)d_in[8];
    float* out = (float*)d_out;

    float *z1, *ssq;
    __half *uhi, *ulo, *w1h, *ghi, *glo, *w2h;
    cudaGetSymbolAddress((void**)&z1,  g_z1);
    cudaGetSymbolAddress((void**)&ssq, g_ssq);
    cudaGetSymbolAddress((void**)&uhi, g_uhi);
    cudaGetSymbolAddress((void**)&ulo, g_ulo);
    cudaGetSymbolAddress((void**)&w1h, g_w1h);
    cudaGetSymbolAddress((void**)&ghi, g_ghi);
    cudaGetSymbolAddress((void**)&glo, g_glo);
    cudaGetSymbolAddress((void**)&w2h, g_w2h);

    cudaFuncSetAttribute(gemm_hmma_f16x2,
                         cudaFuncAttributeMaxDynamicSharedMemorySize, GEMM_SMEM);

    // 1) splits + ssq zeroing, single launch
    split_all_f16<<<(N4_ALL + 255) / 256, 256>>>(u, W_in, W_out,
                                                 uhi, ulo, w1h, w2h, ssq);

    // 2) in_proj GEMM (HMMA fp16 2-term) + bias -> z1; ssq fused in epilogue
    {
        dim3 grid(TWOE / GN, BT / GM);
        gemm_hmma_f16x2<<<grid, 256, GEMM_SMEM>>>(uhi, ulo, w1h, b_in, z1,
                                                  BT, TWOE, D_, ssq);
    }
    // 3) conv + gate (vectorized x4, inline row scales) -> gated fp16 hi/lo
    conv_gate_v4<<<(BT * E_ / 4) / 256, 256>>>(z1, ssq, innw, conv_w, conv_b, ghi, glo);

    // 4) out_proj GEMM + bias -> out (raw)
    {
        dim3 grid(D_ / GN, BT / GM);
        gemm_hmma_f16x2<<<grid, 256, GEMM_SMEM>>>(ghi, glo, w2h, b_out, out,
                                                  BT, D_, E_, nullptr);
    }
    // 5) in-place RMSNorm on out rows
    out_rmsnorm<<<BT, 256>>>(out, outnw);
}